// round 1
// baseline (speedup 1.0000x reference)
#include <cuda_runtime.h>

// Problem shape (fixed for this dataset entry):
//   x: [8, 2048, 1024], Wk/Wq/Wv: [1024, 1024]
//   outputs: out [8,2048,1024] then wei [8,2048,2048], concatenated in d_out.
static constexpr int B_ = 8;
static constexpr int T_ = 2048;
static constexpr int C_ = 1024;
static constexpr int H_ = 1024;

// Scratch (allocation-free rule: __device__ globals)
__device__ float g_q[(size_t)B_ * T_ * H_];
__device__ float g_k[(size_t)B_ * T_ * H_];
__device__ float g_v[(size_t)B_ * T_ * H_];

#define BM 128
#define BN 128
#define BKK 8

// Generic fp32 tiled GEMM.
//   BT = true : C[m,n] = alpha * sum_k A[m*lda + k] * B[n*ldb + k]   (both K-contiguous, "NT")
//   BT = false: C[m,n] = alpha * sum_k A[m*lda + k] * B[k*ldb + n]   ("NN")
// causal: 0 = none
//         1 = skip whole block if bn > bm (upper-triangular block of QK^T; softmax zero-fills)
//         2 = limit K to (bm+1)*BM (wei rows are zero beyond the diagonal)
// Batched via blockIdx.z with element strides sA/sB/sC.
template <bool BT>
__global__ __launch_bounds__(256, 2)
void sgemm_kernel(const float* __restrict__ A, const float* __restrict__ Bmat,
                  float* __restrict__ C,
                  int K, int lda, int ldb, int ldc,
                  long long sA, long long sB, long long sC,
                  float alpha, int causal)
{
    const int bm = blockIdx.y;
    const int bn = blockIdx.x;
    const int bz = blockIdx.z;

    if (causal == 1 && bn > bm) return;
    int Keff = K;
    if (causal == 2) {
        int kl = (bm + 1) * BM;
        Keff = kl < K ? kl : K;
    }

    const float* Ab = A + (long long)bz * sA;
    const float* Bb = Bmat + (long long)bz * sB;
    float* Cb = C + (long long)bz * sC;

    __shared__ float As[BKK][BM];
    __shared__ float Bs[BKK][BN];

    const int tid = threadIdx.x;

    // A tile load: 128 rows x 8 K, one float4 per thread.
    const int arow = tid >> 1;          // 0..127
    const int acol = (tid & 1) << 2;    // 0 or 4
    const float* Ap = Ab + (long long)(bm * BM + arow) * lda + acol;

    // B tile load indices
    const float* Bp;
    int brow = 0, bcol = 0;
    if (BT) {
        Bp = Bb + (long long)(bn * BN + arow) * ldb + acol;
    } else {
        brow = tid >> 5;                // 0..7
        bcol = (tid & 31) << 2;         // 0..124
        Bp = Bb + (long long)brow * ldb + bn * BN + bcol;
    }

    const int tx = tid & 15;
    const int ty = tid >> 4;

    float acc[8][8] = {};

    for (int k0 = 0; k0 < Keff; k0 += BKK) {
        float4 av = *(const float4*)(Ap + k0);
        As[acol + 0][arow] = av.x;
        As[acol + 1][arow] = av.y;
        As[acol + 2][arow] = av.z;
        As[acol + 3][arow] = av.w;
        if (BT) {
            float4 bv = *(const float4*)(Bp + k0);
            Bs[acol + 0][arow] = bv.x;
            Bs[acol + 1][arow] = bv.y;
            Bs[acol + 2][arow] = bv.z;
            Bs[acol + 3][arow] = bv.w;
        } else {
            float4 bv = *(const float4*)(Bp + (long long)k0 * ldb);
            *(float4*)&Bs[brow][bcol] = bv;
        }
        __syncthreads();

#pragma unroll
        for (int k = 0; k < BKK; k++) {
            float a[8], b[8];
#pragma unroll
            for (int i = 0; i < 8; i++) a[i] = As[k][ty * 8 + i];
#pragma unroll
            for (int j = 0; j < 8; j++) b[j] = Bs[k][tx * 8 + j];
#pragma unroll
            for (int i = 0; i < 8; i++)
#pragma unroll
                for (int j = 0; j < 8; j++)
                    acc[i][j] = fmaf(a[i], b[j], acc[i][j]);
        }
        __syncthreads();
    }

#pragma unroll
    for (int i = 0; i < 8; i++) {
        const int r = bm * BM + ty * 8 + i;
        float* Cr = Cb + (long long)r * ldc + bn * BN + tx * 8;
#pragma unroll
        for (int j = 0; j < 8; j += 4) {
            float4 v4;
            v4.x = acc[i][j + 0] * alpha;
            v4.y = acc[i][j + 1] * alpha;
            v4.z = acc[i][j + 2] * alpha;
            v4.w = acc[i][j + 3] * alpha;
            *(float4*)(Cr + j) = v4;
        }
    }
}

// In-place causal row softmax on W (layout [B*T, T]).
// Row `row` (t = row % T): softmax over [0, t], exact zeros for (t, T).
__global__ void softmax_kernel(float* __restrict__ W, int T)
{
    const long long row = blockIdx.x;
    const int t = (int)(row % T);
    float* p = W + row * (long long)T;
    const int n = t + 1;
    const int tid = threadIdx.x;
    const int nthr = blockDim.x;

    __shared__ float red[32];

    // pass 1: max
    float m = -3.4e38f;
    for (int i = tid; i < n; i += nthr) m = fmaxf(m, p[i]);
#pragma unroll
    for (int o = 16; o; o >>= 1) m = fmaxf(m, __shfl_xor_sync(0xffffffffu, m, o));
    if ((tid & 31) == 0) red[tid >> 5] = m;
    __syncthreads();
    if (tid < 32) {
        float mb = (tid < (nthr >> 5)) ? red[tid] : -3.4e38f;
#pragma unroll
        for (int o = 16; o; o >>= 1) mb = fmaxf(mb, __shfl_xor_sync(0xffffffffu, mb, o));
        if (tid == 0) red[0] = mb;
    }
    __syncthreads();
    m = red[0];
    __syncthreads();

    // pass 2: exp + sum (store exp in place)
    float s = 0.f;
    for (int i = tid; i < n; i += nthr) {
        float e = expf(p[i] - m);
        p[i] = e;
        s += e;
    }
#pragma unroll
    for (int o = 16; o; o >>= 1) s += __shfl_xor_sync(0xffffffffu, s, o);
    if ((tid & 31) == 0) red[tid >> 5] = s;
    __syncthreads();
    if (tid < 32) {
        float sb = (tid < (nthr >> 5)) ? red[tid] : 0.f;
#pragma unroll
        for (int o = 16; o; o >>= 1) sb += __shfl_xor_sync(0xffffffffu, sb, o);
        if (tid == 0) red[0] = sb;
    }
    __syncthreads();
    const float inv = 1.f / red[0];

    // pass 3: normalize + zero-fill tail
    for (int i = tid; i < n; i += nthr) p[i] *= inv;
    for (int i = n + tid; i < T; i += nthr) p[i] = 0.f;
}

extern "C" void kernel_launch(void* const* d_in, const int* in_sizes, int n_in,
                              void* d_out, int out_size)
{
    (void)in_sizes; (void)n_in; (void)out_size;
    const float* x  = (const float*)d_in[0];
    const float* Wk = (const float*)d_in[1];
    const float* Wq = (const float*)d_in[2];
    const float* Wv = (const float*)d_in[3];

    float* out = (float*)d_out;                       // [B, T, H]
    float* wei = out + (size_t)B_ * T_ * H_;          // [B, T, T]

    float *q, *k, *v;
    cudaGetSymbolAddress((void**)&q, g_q);
    cudaGetSymbolAddress((void**)&k, g_k);
    cudaGetSymbolAddress((void**)&v, g_v);

    const dim3 blk(256);

    // 1) Projections: Y[m,h] = sum_c x[m,c] * W[h,c]   (M=B*T=16384, N=H=1024, K=C=1024)
    const dim3 gp(H_ / BN, (B_ * T_) / BM, 1);
    sgemm_kernel<true><<<gp, blk>>>(x, Wq, q, C_, C_, C_, H_, 0, 0, 0, 1.0f, 0);
    sgemm_kernel<true><<<gp, blk>>>(x, Wk, k, C_, C_, C_, H_, 0, 0, 0, 1.0f, 0);
    sgemm_kernel<true><<<gp, blk>>>(x, Wv, v, C_, C_, C_, H_, 0, 0, 0, 1.0f, 0);

    // 2) Logits into wei region: S[b,t,s] = (1/32) * q[b,t,:] . k[b,s,:]
    //    causal=1 skips strictly-upper blocks (softmax zero-fills those).
    const dim3 gs(T_ / BN, T_ / BM, B_);
    sgemm_kernel<true><<<gs, blk>>>(q, k, wei, H_, H_, H_, T_,
                                    (long long)T_ * H_, (long long)T_ * H_,
                                    (long long)T_ * T_, 0.03125f, 1);

    // 3) In-place causal softmax over each row of wei.
    softmax_kernel<<<B_ * T_, 256>>>(wei, T_);

    // 4) out[b,t,h] = sum_s wei[b,t,s] * v[b,s,h]   causal=2 limits K to the diagonal.
    const dim3 go(H_ / BN, T_ / BM, B_);
    sgemm_kernel<false><<<go, blk>>>(wei, v, out, T_, T_, H_, H_,
                                     (long long)T_ * T_, (long long)T_ * H_,
                                     (long long)T_ * H_, 1.0f, 2);
}

// round 3
// speedup vs baseline: 1.5986x; 1.5986x over previous
#include <cuda_runtime.h>
#include <cstdint>

// ---------------- problem shape ----------------
static constexpr int B_ = 8;
static constexpr int T_ = 2048;
static constexpr int C_ = 1024;
static constexpr int H_ = 1024;

// ---------------- scratch (__device__ globals; allocation-free rule) ----------------
__device__ float g_xh[(size_t)B_ * T_ * C_];
__device__ float g_xl[(size_t)B_ * T_ * C_];
__device__ float g_wqh[(size_t)H_ * C_];
__device__ float g_wql[(size_t)H_ * C_];
__device__ float g_wkh[(size_t)H_ * C_];
__device__ float g_wkl[(size_t)H_ * C_];
__device__ float g_wvh[(size_t)H_ * C_];
__device__ float g_wvl[(size_t)H_ * C_];
__device__ float g_qh[(size_t)B_ * T_ * H_];
__device__ float g_ql[(size_t)B_ * T_ * H_];
__device__ float g_kh[(size_t)B_ * T_ * H_];
__device__ float g_kl[(size_t)B_ * T_ * H_];
__device__ float g_vth[(size_t)B_ * H_ * T_];   // v transposed per batch: [b][h][t]
__device__ float g_vtl[(size_t)B_ * H_ * T_];
__device__ float g_weih[(size_t)B_ * T_ * T_];
__device__ float g_weil[(size_t)B_ * T_ * T_];

// ---------------- helpers ----------------
__device__ __forceinline__ uint32_t smem_u32(const void* p) {
    uint32_t a;
    asm("{ .reg .u64 t; cvta.to.shared.u64 t, %1; cvt.u32.u64 %0, t; }" : "=r"(a) : "l"(p));
    return a;
}
__device__ __forceinline__ float tf32r(float x) {
    float y;
    asm("cvt.rna.tf32.f32 %0, %1;" : "=f"(y) : "f"(x));
    return y;
}
__device__ __forceinline__ void cpa16(uint32_t dst, const float* src) {
    asm volatile("cp.async.cg.shared.global [%0], [%1], 16;" :: "r"(dst), "l"(src));
}
__device__ __forceinline__ void cp_commit() {
    asm volatile("cp.async.commit_group;" ::: "memory");
}
template <int N>
__device__ __forceinline__ void cp_wait() {
    asm volatile("cp.async.wait_group %0;" :: "n"(N) : "memory");
}
// D += A*B, m16n8k8 tf32 (tensor pipe, non-'a' PTX)
__device__ __forceinline__ void mma8(float* d, const uint32_t* a, const uint32_t* b) {
    asm volatile(
        "mma.sync.aligned.m16n8k8.row.col.f32.tf32.tf32.f32 "
        "{%0,%1,%2,%3},{%4,%5,%6,%7},{%8,%9},{%0,%1,%2,%3};"
        : "+f"(d[0]), "+f"(d[1]), "+f"(d[2]), "+f"(d[3])
        : "r"(a[0]), "r"(a[1]), "r"(a[2]), "r"(a[3]), "r"(b[0]), "r"(b[1]));
}

// ---------------- TF32x3 NT GEMM via mma.sync ----------------
// C[m,n] = alpha * sum_k A[m,k]*B[n,k], A=(Ahi+Alo), B=(Bhi+Blo) tf32 pairs.
// CTA tile 128x128, BK=16, 256 threads (2x4 warps, 64x32 warp tiles).
// SMEM per stage: 4 arrays of [128][20] floats (pad -> conflict-free frag LDS).
// EPI=0: C0 = result*alpha.  EPI=1: C0/C1 = tf32 hi/lo split of result.
// causal: 0 none; 1 skip block if bn>bm; 2 Keff=min(K,(bm+1)*128).
static constexpr int GEMM_SMEM = 2 * 40960;   // 80 KB (double buffer)

template <int EPI>
__global__ __launch_bounds__(256, 2)
void mma_nt(const float* __restrict__ Ahi, const float* __restrict__ Alo,
            const float* __restrict__ Bhi, const float* __restrict__ Blo,
            float* __restrict__ C0, float* __restrict__ C1,
            int K, int lda, int ldb, int ldc,
            long long sA, long long sB, long long sC,
            float alpha, int causal)
{
    extern __shared__ float sm[];
    const int bm = blockIdx.y, bn = blockIdx.x, bz = blockIdx.z;
    if (causal == 1 && bn > bm) return;
    int Keff = K;
    if (causal == 2) { int kl = (bm + 1) * 128; Keff = kl < K ? kl : K; }
    const int nk = Keff / 16;

    const float* Ah = Ahi + (size_t)bz * sA;
    const float* Al = Alo + (size_t)bz * sA;
    const float* Bh = Bhi + (size_t)bz * sB;
    const float* Bl = Blo + (size_t)bz * sB;

    const int tid = threadIdx.x;
    const int lane = tid & 31, w = tid >> 5;
    const int wm = w & 1, wn = w >> 1;          // warp grid 2 (M) x 4 (N)
    const uint32_t sbase = smem_u32(sm);

    // stage loader: 4 arrays x 128 rows x 16 floats, dst row stride 20 floats (80B)
    auto load_stage = [&](int kt, int s) {
        const int k0 = kt * 16;
        const uint32_t dst = sbase + (uint32_t)s * 40960u;
#pragma unroll
        for (int t = 0; t < 2; t++) {
            const int idx = t * 256 + tid;       // 0..511 float4 slots per array
            const int row = idx >> 2, j = idx & 3;
            const uint32_t off = (uint32_t)(row * 80 + j * 16);
            const size_t ga = (size_t)(bm * 128 + row) * lda + k0 + 4 * j;
            const size_t gb = (size_t)(bn * 128 + row) * ldb + k0 + 4 * j;
            cpa16(dst + off,          Ah + ga);
            cpa16(dst + 10240u + off, Al + ga);
            cpa16(dst + 20480u + off, Bh + gb);
            cpa16(dst + 30720u + off, Bl + gb);
        }
        cp_commit();
    };

    float acc[4][4][4];
#pragma unroll
    for (int i = 0; i < 4; i++)
#pragma unroll
        for (int j = 0; j < 4; j++)
#pragma unroll
            for (int r = 0; r < 4; r++) acc[i][j][r] = 0.f;

    load_stage(0, 0);

    const int gr = lane >> 2, tc = lane & 3;
    const int abase0 = (wm * 64 + gr) * 20 + tc;
    const int bbase0 = (wn * 32 + gr) * 20 + tc;

    for (int kt = 0; kt < nk; kt++) {
        const int s = kt & 1;
        if (kt + 1 < nk) { load_stage(kt + 1, s ^ 1); cp_wait<1>(); }
        else             { cp_wait<0>(); }
        __syncthreads();

        const uint32_t* pAh = (const uint32_t*)sm + s * 10240;
        const uint32_t* pAl = pAh + 2560;
        const uint32_t* pBh = pAh + 5120;
        const uint32_t* pBl = pAh + 7680;

#pragma unroll
        for (int ks = 0; ks < 2; ks++) {
            const int ka = abase0 + ks * 8;
            const int kb = bbase0 + ks * 8;

            uint32_t aH[4][4], bH[4][2];
#pragma unroll
            for (int fm = 0; fm < 4; fm++) {
                const int o = ka + fm * 320;     // fm*16 rows * 20
                aH[fm][0] = pAh[o];       aH[fm][1] = pAh[o + 160];
                aH[fm][2] = pAh[o + 4];   aH[fm][3] = pAh[o + 164];
            }
#pragma unroll
            for (int fn = 0; fn < 4; fn++) {
                const int o = kb + fn * 160;     // fn*8 rows * 20
                bH[fn][0] = pBh[o];       bH[fn][1] = pBh[o + 4];
            }
            // pass 1: hi*hi
#pragma unroll
            for (int fm = 0; fm < 4; fm++)
#pragma unroll
                for (int fn = 0; fn < 4; fn++) mma8(acc[fm][fn], aH[fm], bH[fn]);
            // pass 2: lo*hi
            {
                uint32_t aL[4][4];
#pragma unroll
                for (int fm = 0; fm < 4; fm++) {
                    const int o = ka + fm * 320;
                    aL[fm][0] = pAl[o];       aL[fm][1] = pAl[o + 160];
                    aL[fm][2] = pAl[o + 4];   aL[fm][3] = pAl[o + 164];
                }
#pragma unroll
                for (int fm = 0; fm < 4; fm++)
#pragma unroll
                    for (int fn = 0; fn < 4; fn++) mma8(acc[fm][fn], aL[fm], bH[fn]);
            }
            // pass 3: hi*lo
            {
                uint32_t bL[4][2];
#pragma unroll
                for (int fn = 0; fn < 4; fn++) {
                    const int o = kb + fn * 160;
                    bL[fn][0] = pBl[o];       bL[fn][1] = pBl[o + 4];
                }
#pragma unroll
                for (int fm = 0; fm < 4; fm++)
#pragma unroll
                    for (int fn = 0; fn < 4; fn++) mma8(acc[fm][fn], aH[fm], bL[fn]);
            }
        }
        __syncthreads();
    }

    // ---- epilogue ----
#pragma unroll
    for (int fm = 0; fm < 4; fm++) {
        const int r0 = bm * 128 + wm * 64 + fm * 16 + gr;
#pragma unroll
        for (int fn = 0; fn < 4; fn++) {
            const int c0 = bn * 128 + wn * 32 + fn * 8 + 2 * tc;
            const size_t o0 = (size_t)bz * sC + (size_t)r0 * ldc + c0;
            const size_t o1 = o0 + (size_t)8 * ldc;
            const float* a = acc[fm][fn];
            if (EPI == 0) {
                float2 v0 = make_float2(a[0] * alpha, a[1] * alpha);
                float2 v1 = make_float2(a[2] * alpha, a[3] * alpha);
                *(float2*)(C0 + o0) = v0;
                *(float2*)(C0 + o1) = v1;
            } else {
                float h0 = tf32r(a[0]), h1 = tf32r(a[1]), h2 = tf32r(a[2]), h3 = tf32r(a[3]);
                *(float2*)(C0 + o0) = make_float2(h0, h1);
                *(float2*)(C0 + o1) = make_float2(h2, h3);
                *(float2*)(C1 + o0) = make_float2(tf32r(a[0] - h0), tf32r(a[1] - h1));
                *(float2*)(C1 + o1) = make_float2(tf32r(a[2] - h2), tf32r(a[3] - h3));
            }
        }
    }
}

// ---------------- elementwise tf32 split ----------------
__global__ void split_kernel(const float* __restrict__ src,
                             float* __restrict__ hi, float* __restrict__ lo, int n4)
{
    const int i = blockIdx.x * blockDim.x + threadIdx.x;
    if (i >= n4) return;
    const float4 v = ((const float4*)src)[i];
    float4 h, l;
    h.x = tf32r(v.x); l.x = tf32r(v.x - h.x);
    h.y = tf32r(v.y); l.y = tf32r(v.y - h.y);
    h.z = tf32r(v.z); l.z = tf32r(v.z - h.z);
    h.w = tf32r(v.w); l.w = tf32r(v.w - h.w);
    ((float4*)hi)[i] = h;
    ((float4*)lo)[i] = l;
}

// ---------------- causal softmax (in-place) + fused tf32 split ----------------
__global__ void softmax_split_kernel(float* __restrict__ W,
                                     float* __restrict__ Wh, float* __restrict__ Wl, int T)
{
    const long long row = blockIdx.x;
    const int t = (int)(row % T);
    float* p  = W  + row * (long long)T;
    float* ph = Wh + row * (long long)T;
    float* pl = Wl + row * (long long)T;
    const int n = t + 1;
    const int tid = threadIdx.x;
    const int nthr = blockDim.x;

    __shared__ float red[32];

    float m = -3.4e38f;
    for (int i = tid; i < n; i += nthr) m = fmaxf(m, p[i]);
#pragma unroll
    for (int o = 16; o; o >>= 1) m = fmaxf(m, __shfl_xor_sync(0xffffffffu, m, o));
    if ((tid & 31) == 0) red[tid >> 5] = m;
    __syncthreads();
    if (tid < 32) {
        float mb = (tid < (nthr >> 5)) ? red[tid] : -3.4e38f;
#pragma unroll
        for (int o = 16; o; o >>= 1) mb = fmaxf(mb, __shfl_xor_sync(0xffffffffu, mb, o));
        if (tid == 0) red[0] = mb;
    }
    __syncthreads();
    m = red[0];
    __syncthreads();

    float s = 0.f;
    for (int i = tid; i < n; i += nthr) {
        float e = expf(p[i] - m);
        p[i] = e;
        s += e;
    }
#pragma unroll
    for (int o = 16; o; o >>= 1) s += __shfl_xor_sync(0xffffffffu, s, o);
    if ((tid & 31) == 0) red[tid >> 5] = s;
    __syncthreads();
    if (tid < 32) {
        float sb = (tid < (nthr >> 5)) ? red[tid] : 0.f;
#pragma unroll
        for (int o = 16; o; o >>= 1) sb += __shfl_xor_sync(0xffffffffu, sb, o);
        if (tid == 0) red[0] = sb;
    }
    __syncthreads();
    const float inv = 1.f / red[0];

    for (int i = tid; i < n; i += nthr) {
        const float wv = p[i] * inv;
        p[i] = wv;
        const float h = tf32r(wv);
        ph[i] = h;
        pl[i] = tf32r(wv - h);
    }
    for (int i = n + tid; i < T; i += nthr) { p[i] = 0.f; ph[i] = 0.f; pl[i] = 0.f; }
}

// ---------------- launch ----------------
extern "C" void kernel_launch(void* const* d_in, const int* in_sizes, int n_in,
                              void* d_out, int out_size)
{
    (void)in_sizes; (void)n_in; (void)out_size;
    const float* x  = (const float*)d_in[0];
    const float* Wk = (const float*)d_in[1];
    const float* Wq = (const float*)d_in[2];
    const float* Wv = (const float*)d_in[3];

    float* out = (float*)d_out;                      // [B, T, H]
    float* wei = out + (size_t)B_ * T_ * H_;         // [B, T, T]

    float *xh, *xl, *wqh, *wql, *wkh, *wkl, *wvh, *wvl;
    float *qh, *ql, *kh, *kl, *vth, *vtl, *weih, *weil;
    cudaGetSymbolAddress((void**)&xh, g_xh);   cudaGetSymbolAddress((void**)&xl, g_xl);
    cudaGetSymbolAddress((void**)&wqh, g_wqh); cudaGetSymbolAddress((void**)&wql, g_wql);
    cudaGetSymbolAddress((void**)&wkh, g_wkh); cudaGetSymbolAddress((void**)&wkl, g_wkl);
    cudaGetSymbolAddress((void**)&wvh, g_wvh); cudaGetSymbolAddress((void**)&wvl, g_wvl);
    cudaGetSymbolAddress((void**)&qh, g_qh);   cudaGetSymbolAddress((void**)&ql, g_ql);
    cudaGetSymbolAddress((void**)&kh, g_kh);   cudaGetSymbolAddress((void**)&kl, g_kl);
    cudaGetSymbolAddress((void**)&vth, g_vth); cudaGetSymbolAddress((void**)&vtl, g_vtl);
    cudaGetSymbolAddress((void**)&weih, g_weih); cudaGetSymbolAddress((void**)&weil, g_weil);

    cudaFuncSetAttribute(mma_nt<0>, cudaFuncAttributeMaxDynamicSharedMemorySize, GEMM_SMEM);
    cudaFuncSetAttribute(mma_nt<1>, cudaFuncAttributeMaxDynamicSharedMemorySize, GEMM_SMEM);

    // 1) split x and weights to tf32 hi/lo
    {
        const int n4x = (B_ * T_ * C_) / 4;
        split_kernel<<<(n4x + 255) / 256, 256>>>(x, xh, xl, n4x);
        const int n4w = (H_ * C_) / 4;
        split_kernel<<<(n4w + 255) / 256, 256>>>(Wq, wqh, wql, n4w);
        split_kernel<<<(n4w + 255) / 256, 256>>>(Wk, wkh, wkl, n4w);
        split_kernel<<<(n4w + 255) / 256, 256>>>(Wv, wvh, wvl, n4w);
    }

    const dim3 blk(256);

    // 2) projections (epilogue writes tf32 hi/lo directly)
    {
        const dim3 g(H_ / 128, (B_ * T_) / 128, 1);
        mma_nt<1><<<g, blk, GEMM_SMEM>>>(xh, xl, wqh, wql, qh, ql,
                                         C_, C_, C_, H_, 0, 0, 0, 1.f, 0);
        mma_nt<1><<<g, blk, GEMM_SMEM>>>(xh, xl, wkh, wkl, kh, kl,
                                         C_, C_, C_, H_, 0, 0, 0, 1.f, 0);
    }
    //    vT[b,h,t] = Wv[h,:]·x[b,t,:]
    {
        const dim3 g(T_ / 128, H_ / 128, B_);
        mma_nt<1><<<g, blk, GEMM_SMEM>>>(wvh, wvl, xh, xl, vth, vtl,
                                         C_, C_, C_, T_,
                                         0, (long long)T_ * C_, (long long)H_ * T_, 1.f, 0);
    }

    // 3) logits: wei[b,t,s] = (1/32) q[b,t,:]·k[b,s,:]  (causal block skip)
    {
        const dim3 g(T_ / 128, T_ / 128, B_);
        mma_nt<0><<<g, blk, GEMM_SMEM>>>(qh, ql, kh, kl, wei, nullptr,
                                         H_, H_, H_, T_,
                                         (long long)T_ * H_, (long long)T_ * H_,
                                         (long long)T_ * T_, 0.03125f, 1);
    }

    // 4) causal softmax in-place + hi/lo split of wei
    softmax_split_kernel<<<B_ * T_, 256>>>(wei, weih, weil, T_);

    // 5) out[b,t,h] = sum_s wei[b,t,s] * vT[b,h,s]  (causal K limit)
    {
        const dim3 g(H_ / 128, T_ / 128, B_);
        mma_nt<0><<<g, blk, GEMM_SMEM>>>(weih, weil, vth, vtl, out, nullptr,
                                         T_, T_, T_, H_,
                                         (long long)T_ * T_, (long long)H_ * T_,
                                         (long long)T_ * H_, 1.f, 2);
    }
}

// round 4
// speedup vs baseline: 1.7316x; 1.0832x over previous
#include <cuda_runtime.h>
#include <cstdint>

// ---------------- problem shape ----------------
static constexpr int B_ = 8;
static constexpr int T_ = 2048;
static constexpr int C_ = 1024;
static constexpr int H_ = 1024;

// ---------------- scratch (__device__ globals) ----------------
// All hi/lo arrays are stored K-PERMUTED: within each 16-column block of the
// contraction dimension, column c is stored at position (c%4)*4 + c/4 (4x4
// transpose, an involution). Both GEMM operands use the same permutation, so
// dot products are unchanged.
__device__ float g_xh[(size_t)B_ * T_ * C_];
__device__ float g_xl[(size_t)B_ * T_ * C_];
__device__ float g_wqh[(size_t)H_ * C_];
__device__ float g_wql[(size_t)H_ * C_];
__device__ float g_wkh[(size_t)H_ * C_];
__device__ float g_wkl[(size_t)H_ * C_];
__device__ float g_wvh[(size_t)H_ * C_];
__device__ float g_wvl[(size_t)H_ * C_];
__device__ float g_qh[(size_t)B_ * T_ * H_];
__device__ float g_ql[(size_t)B_ * T_ * H_];
__device__ float g_kh[(size_t)B_ * T_ * H_];
__device__ float g_kl[(size_t)B_ * T_ * H_];
__device__ float g_vth[(size_t)B_ * H_ * T_];   // v transposed: [b][h][t]
__device__ float g_vtl[(size_t)B_ * H_ * T_];
__device__ float g_weih[(size_t)B_ * T_ * T_];
__device__ float g_weil[(size_t)B_ * T_ * T_];

// ---------------- helpers ----------------
__device__ __forceinline__ uint32_t smem_u32(const void* p) {
    uint32_t a;
    asm("{ .reg .u64 t; cvta.to.shared.u64 t, %1; cvt.u32.u64 %0, t; }" : "=r"(a) : "l"(p));
    return a;
}
__device__ __forceinline__ float tf32r(float x) {
    float y;
    asm("cvt.rna.tf32.f32 %0, %1;" : "=f"(y) : "f"(x));
    return y;
}
// permuted index within 16-block (involution)
__device__ __forceinline__ int pidx(int c) {
    return (c & ~15) | ((c & 3) << 2) | ((c >> 2) & 3);
}
__device__ __forceinline__ void cpa16(uint32_t dst, const float* src) {
    asm volatile("cp.async.cg.shared.global [%0], [%1], 16;" :: "r"(dst), "l"(src));
}
__device__ __forceinline__ void cp_commit() {
    asm volatile("cp.async.commit_group;" ::: "memory");
}
template <int N>
__device__ __forceinline__ void cp_wait() {
    asm volatile("cp.async.wait_group %0;" :: "n"(N) : "memory");
}
// D += A*B, m16n8k8 tf32
__device__ __forceinline__ void mma8(float* d, float a0, float a1, float a2, float a3,
                                     float b0, float b1) {
    asm volatile(
        "mma.sync.aligned.m16n8k8.row.col.f32.tf32.tf32.f32 "
        "{%0,%1,%2,%3},{%4,%5,%6,%7},{%8,%9},{%0,%1,%2,%3};"
        : "+f"(d[0]), "+f"(d[1]), "+f"(d[2]), "+f"(d[3])
        : "r"(__float_as_uint(a0)), "r"(__float_as_uint(a1)),
          "r"(__float_as_uint(a2)), "r"(__float_as_uint(a3)),
          "r"(__float_as_uint(b0)), "r"(__float_as_uint(b1)));
}

// ---------------- TF32x3 NT GEMM via mma.sync (permuted-K operands) ----------------
// C[m,n] = alpha * sum_k A[m,k]*B[n,k]. CTA 128x128, BK=16, 256 thr (2x4 warps).
// SMEM stage: 4 arrays [128][16] floats (8KB each), K-cols pre-permuted in gmem,
// so each thread's fragment (cols tc,tc+4,tc+8,tc+12 of one row) is ONE LDS.128.
// EPI=0: C0 = result*alpha (linear cols). EPI=1: C0/C1 = tf32 hi/lo, permuted cols.
// PASSES=3: hi*hi + lo*hi + hi*lo. PASSES=2: hi*hi + lo*hi (skip A_hi*B_lo).
// causal: 0 none; 1 skip block if bn>bm; 2 Keff=min(K,(bm+1)*128).
static constexpr int GEMM_SMEM = 2 * 32768;   // 64 KB double buffer

template <int EPI, int PASSES>
__global__ __launch_bounds__(256, 2)
void mma_nt(const float* __restrict__ Ahi, const float* __restrict__ Alo,
            const float* __restrict__ Bhi, const float* __restrict__ Blo,
            float* __restrict__ C0, float* __restrict__ C1,
            int K, int lda, int ldb, int ldc,
            long long sA, long long sB, long long sC,
            float alpha, int causal)
{
    extern __shared__ float sm[];
    const int bm = blockIdx.y, bn = blockIdx.x, bz = blockIdx.z;
    if (causal == 1 && bn > bm) return;
    int Keff = K;
    if (causal == 2) { int kl = (bm + 1) * 128; Keff = kl < K ? kl : K; }
    const int nk = Keff / 16;

    const float* Ah = Ahi + (size_t)bz * sA;
    const float* Al = Alo + (size_t)bz * sA;
    const float* Bh = Bhi + (size_t)bz * sB;
    const float* Bl = Blo + (size_t)bz * sB;

    const int tid = threadIdx.x;
    const int lane = tid & 31, w = tid >> 5;
    const int wm = w & 1, wn = w >> 1;          // 2 (M) x 4 (N) warp grid
    const int gr = lane >> 2, tc = lane & 3;
    const uint32_t sbase = smem_u32(sm);

    // stage loader: 4 arrays x 128 rows x 16 floats (64B rows, no pad)
    auto load_stage = [&](int kt, int s) {
        const int k0 = kt * 16;
        const uint32_t dst = sbase + (uint32_t)s * 32768u;
#pragma unroll
        for (int t = 0; t < 2; t++) {
            const int idx = t * 256 + tid;       // 0..511 float4 slots per array
            const int row = idx >> 2, j = idx & 3;
            const uint32_t off = (uint32_t)(row * 64 + j * 16);
            const size_t ga = (size_t)(bm * 128 + row) * lda + k0 + 4 * j;
            const size_t gb = (size_t)(bn * 128 + row) * ldb + k0 + 4 * j;
            cpa16(dst + off,           Ah + ga);
            cpa16(dst + 8192u + off,   Al + ga);
            cpa16(dst + 16384u + off,  Bh + gb);
            if (PASSES == 3) cpa16(dst + 24576u + off, Bl + gb);
        }
        cp_commit();
    };

    float acc[4][4][4];
#pragma unroll
    for (int i = 0; i < 4; i++)
#pragma unroll
        for (int j = 0; j < 4; j++)
#pragma unroll
            for (int r = 0; r < 4; r++) acc[i][j][r] = 0.f;

    load_stage(0, 0);

    const int rbB = (wn * 32 + gr) * 4 + tc;          // B frag base (float4 units)
    const int rbA = (wm * 64 + gr) * 4 + tc;          // A frag base

    for (int kt = 0; kt < nk; kt++) {
        const int s = kt & 1;
        if (kt + 1 < nk) { load_stage(kt + 1, s ^ 1); cp_wait<1>(); }
        else             { cp_wait<0>(); }
        __syncthreads();

        const float4* S   = (const float4*)sm + s * 2048;
        const float4* pAh = S;
        const float4* pAl = S + 512;
        const float4* pBh = S + 1024;
        const float4* pBl = S + 1536;

        // B-hi fragments: one float4 per fn covers both k-halves
        float4 bh0 = pBh[rbB], bh1 = pBh[rbB + 32], bh2 = pBh[rbB + 64], bh3 = pBh[rbB + 96];

        // passes 1+2 (hi*hi, lo*hi), fm-major to bound register life
#pragma unroll
        for (int fm = 0; fm < 4; fm++) {
            const int ra = rbA + fm * 64;                 // fm*16 rows * 4
            float4 ah0 = pAh[ra], ah1 = pAh[ra + 32];     // rows gr, gr+8
            float4 al0 = pAl[ra], al1 = pAl[ra + 32];
#pragma unroll
            for (int fn = 0; fn < 4; fn++) {
                const float4 bh = fn == 0 ? bh0 : fn == 1 ? bh1 : fn == 2 ? bh2 : bh3;
                float* a = acc[fm][fn];
                mma8(a, ah0.x, ah1.x, ah0.y, ah1.y, bh.x, bh.y);   // ks0 hi*hi
                mma8(a, al0.x, al1.x, al0.y, al1.y, bh.x, bh.y);   // ks0 lo*hi
                mma8(a, ah0.z, ah1.z, ah0.w, ah1.w, bh.z, bh.w);   // ks1 hi*hi
                mma8(a, al0.z, al1.z, al0.w, al1.w, bh.z, bh.w);   // ks1 lo*hi
            }
        }

        if (PASSES == 3) {   // pass 3: hi*lo
            float4 bl0 = pBl[rbB], bl1 = pBl[rbB + 32], bl2 = pBl[rbB + 64], bl3 = pBl[rbB + 96];
#pragma unroll
            for (int fm = 0; fm < 4; fm++) {
                const int ra = rbA + fm * 64;
                float4 ah0 = pAh[ra], ah1 = pAh[ra + 32];
#pragma unroll
                for (int fn = 0; fn < 4; fn++) {
                    const float4 bl = fn == 0 ? bl0 : fn == 1 ? bl1 : fn == 2 ? bl2 : bl3;
                    float* a = acc[fm][fn];
                    mma8(a, ah0.x, ah1.x, ah0.y, ah1.y, bl.x, bl.y);
                    mma8(a, ah0.z, ah1.z, ah0.w, ah1.w, bl.z, bl.w);
                }
            }
        }
        __syncthreads();
    }

    // ---- epilogue ----
#pragma unroll
    for (int fm = 0; fm < 4; fm++) {
        const int r0 = bm * 128 + wm * 64 + fm * 16 + gr;
#pragma unroll
        for (int fn = 0; fn < 4; fn++) {
            const int c0 = bn * 128 + wn * 32 + fn * 8 + 2 * tc;
            const size_t b0 = (size_t)bz * sC + (size_t)r0 * ldc;
            const size_t b8 = b0 + (size_t)8 * ldc;
            const float* a = acc[fm][fn];
            if (EPI == 0) {
                *(float2*)(C0 + b0 + c0) = make_float2(a[0] * alpha, a[1] * alpha);
                *(float2*)(C0 + b8 + c0) = make_float2(a[2] * alpha, a[3] * alpha);
            } else {
                const int cp0 = pidx(c0), cp1 = pidx(c0 + 1);
                float h0 = tf32r(a[0]), h1 = tf32r(a[1]), h2 = tf32r(a[2]), h3 = tf32r(a[3]);
                C0[b0 + cp0] = h0;  C0[b0 + cp1] = h1;
                C0[b8 + cp0] = h2;  C0[b8 + cp1] = h3;
                C1[b0 + cp0] = tf32r(a[0] - h0);  C1[b0 + cp1] = tf32r(a[1] - h1);
                C1[b8 + cp0] = tf32r(a[2] - h2);  C1[b8 + cp1] = tf32r(a[3] - h3);
            }
        }
    }
}

// ---------------- elementwise tf32 split, writing K-permuted layout ----------------
// stored[s] = split(src[pidx(s)]): gather 4 scalars, write one float4.
__global__ void split_kernel(const float* __restrict__ src,
                             float* __restrict__ hi, float* __restrict__ lo, int n4)
{
    const int i = blockIdx.x * blockDim.x + threadIdx.x;
    if (i >= n4) return;
    const int blk = (i & ~3) * 4;     // 16-block base (float units)
    const int j = i & 3;
    float4 h, l;
    {
        float v = src[blk + j];      h.x = tf32r(v); l.x = tf32r(v - h.x);
        v = src[blk + j + 4];        h.y = tf32r(v); l.y = tf32r(v - h.y);
        v = src[blk + j + 8];        h.z = tf32r(v); l.z = tf32r(v - h.z);
        v = src[blk + j + 12];       h.w = tf32r(v); l.w = tf32r(v - h.w);
    }
    ((float4*)hi)[i] = h;
    ((float4*)lo)[i] = l;
}

// ---------------- causal softmax (in-place) + tf32 split (permuted cols) ----------------
__global__ void softmax_split_kernel(float* __restrict__ W,
                                     float* __restrict__ Wh, float* __restrict__ Wl, int T)
{
    const long long row = blockIdx.x;
    const int t = (int)(row % T);
    float* p  = W  + row * (long long)T;
    float* ph = Wh + row * (long long)T;
    float* pl = Wl + row * (long long)T;
    const int n = t + 1;
    const int tid = threadIdx.x;
    const int nthr = blockDim.x;

    __shared__ float red[32];

    float m = -3.4e38f;
    for (int i = tid; i < n; i += nthr) m = fmaxf(m, p[i]);
#pragma unroll
    for (int o = 16; o; o >>= 1) m = fmaxf(m, __shfl_xor_sync(0xffffffffu, m, o));
    if ((tid & 31) == 0) red[tid >> 5] = m;
    __syncthreads();
    if (tid < 32) {
        float mb = (tid < (nthr >> 5)) ? red[tid] : -3.4e38f;
#pragma unroll
        for (int o = 16; o; o >>= 1) mb = fmaxf(mb, __shfl_xor_sync(0xffffffffu, mb, o));
        if (tid == 0) red[0] = mb;
    }
    __syncthreads();
    m = red[0];
    __syncthreads();

    float s = 0.f;
    for (int i = tid; i < n; i += nthr) {
        float e = expf(p[i] - m);
        p[i] = e;
        s += e;
    }
#pragma unroll
    for (int o = 16; o; o >>= 1) s += __shfl_xor_sync(0xffffffffu, s, o);
    if ((tid & 31) == 0) red[tid >> 5] = s;
    __syncthreads();
    if (tid < 32) {
        float sb = (tid < (nthr >> 5)) ? red[tid] : 0.f;
#pragma unroll
        for (int o = 16; o; o >>= 1) sb += __shfl_xor_sync(0xffffffffu, sb, o);
        if (tid == 0) red[0] = sb;
    }
    __syncthreads();
    const float inv = 1.f / red[0];

    for (int i = tid; i < n; i += nthr) {
        const float wv = p[i] * inv;
        p[i] = wv;
        const float h = tf32r(wv);
        const int ip = pidx(i);
        ph[ip] = h;
        pl[ip] = tf32r(wv - h);
    }
    for (int i = n + tid; i < T; i += nthr) {
        p[i] = 0.f;
        const int ip = pidx(i);
        ph[ip] = 0.f;
        pl[ip] = 0.f;
    }
}

// ---------------- launch ----------------
extern "C" void kernel_launch(void* const* d_in, const int* in_sizes, int n_in,
                              void* d_out, int out_size)
{
    (void)in_sizes; (void)n_in; (void)out_size;
    const float* x  = (const float*)d_in[0];
    const float* Wk = (const float*)d_in[1];
    const float* Wq = (const float*)d_in[2];
    const float* Wv = (const float*)d_in[3];

    float* out = (float*)d_out;                      // [B, T, H]
    float* wei = out + (size_t)B_ * T_ * H_;         // [B, T, T]

    float *xh, *xl, *wqh, *wql, *wkh, *wkl, *wvh, *wvl;
    float *qh, *ql, *kh, *kl, *vth, *vtl, *weih, *weil;
    cudaGetSymbolAddress((void**)&xh, g_xh);   cudaGetSymbolAddress((void**)&xl, g_xl);
    cudaGetSymbolAddress((void**)&wqh, g_wqh); cudaGetSymbolAddress((void**)&wql, g_wql);
    cudaGetSymbolAddress((void**)&wkh, g_wkh); cudaGetSymbolAddress((void**)&wkl, g_wkl);
    cudaGetSymbolAddress((void**)&wvh, g_wvh); cudaGetSymbolAddress((void**)&wvl, g_wvl);
    cudaGetSymbolAddress((void**)&qh, g_qh);   cudaGetSymbolAddress((void**)&ql, g_ql);
    cudaGetSymbolAddress((void**)&kh, g_kh);   cudaGetSymbolAddress((void**)&kl, g_kl);
    cudaGetSymbolAddress((void**)&vth, g_vth); cudaGetSymbolAddress((void**)&vtl, g_vtl);
    cudaGetSymbolAddress((void**)&weih, g_weih); cudaGetSymbolAddress((void**)&weil, g_weil);

    cudaFuncSetAttribute(mma_nt<0,3>, cudaFuncAttributeMaxDynamicSharedMemorySize, GEMM_SMEM);
    cudaFuncSetAttribute(mma_nt<1,3>, cudaFuncAttributeMaxDynamicSharedMemorySize, GEMM_SMEM);
    cudaFuncSetAttribute(mma_nt<0,2>, cudaFuncAttributeMaxDynamicSharedMemorySize, GEMM_SMEM);

    // 1) split x and weights to tf32 hi/lo (K-permuted storage)
    {
        const int n4x = (B_ * T_ * C_) / 4;
        split_kernel<<<(n4x + 255) / 256, 256>>>(x, xh, xl, n4x);
        const int n4w = (H_ * C_) / 4;
        split_kernel<<<(n4w + 255) / 256, 256>>>(Wq, wqh, wql, n4w);
        split_kernel<<<(n4w + 255) / 256, 256>>>(Wk, wkh, wkl, n4w);
        split_kernel<<<(n4w + 255) / 256, 256>>>(Wv, wvh, wvl, n4w);
    }

    const dim3 blk(256);

    // 2) projections (epilogue writes permuted tf32 hi/lo)
    {
        const dim3 g(H_ / 128, (B_ * T_) / 128, 1);
        mma_nt<1,3><<<g, blk, GEMM_SMEM>>>(xh, xl, wqh, wql, qh, ql,
                                           C_, C_, C_, H_, 0, 0, 0, 1.f, 0);
        mma_nt<1,3><<<g, blk, GEMM_SMEM>>>(xh, xl, wkh, wkl, kh, kl,
                                           C_, C_, C_, H_, 0, 0, 0, 1.f, 0);
    }
    //    vT[b,h,t] = Wv[h,:]·x[b,t,:]
    {
        const dim3 g(T_ / 128, H_ / 128, B_);
        mma_nt<1,3><<<g, blk, GEMM_SMEM>>>(wvh, wvl, xh, xl, vth, vtl,
                                           C_, C_, C_, T_,
                                           0, (long long)T_ * C_, (long long)H_ * T_, 1.f, 0);
    }

    // 3) logits: wei[b,t,s] = (1/32) q[b,t,:]·k[b,s,:]  (causal block skip)
    {
        const dim3 g(T_ / 128, T_ / 128, B_);
        mma_nt<0,3><<<g, blk, GEMM_SMEM>>>(qh, ql, kh, kl, wei, nullptr,
                                           H_, H_, H_, T_,
                                           (long long)T_ * H_, (long long)T_ * H_,
                                           (long long)T_ * T_, 0.03125f, 1);
    }

    // 4) causal softmax in-place + permuted hi/lo split of wei
    softmax_split_kernel<<<B_ * T_, 256>>>(wei, weih, weil, T_);

    // 5) out[b,t,h] = sum_s wei[b,t,s] * vT[b,h,s]  (causal K limit, 2-pass tf32)
    {
        const dim3 g(H_ / 128, T_ / 128, B_);
        mma_nt<0,2><<<g, blk, GEMM_SMEM>>>(weih, weil, vth, vtl, out, nullptr,
                                           T_, T_, T_, H_,
                                           (long long)T_ * T_, (long long)H_ * T_,
                                           (long long)T_ * H_, 1.f, 2);
    }
}

// round 6
// speedup vs baseline: 3.4138x; 1.9715x over previous
#include <cuda_runtime.h>
#include <cuda_fp16.h>
#include <cstdint>

// ---------------- problem shape ----------------
static constexpr int B_ = 8;
static constexpr int T_ = 2048;
static constexpr int C_ = 1024;
static constexpr int H_ = 1024;

// ---------------- scratch (__device__ globals) ----------------
// All hi/lo arrays are fp16, stored PAIR-PERMUTED along the contraction dim:
// within each 32-element K-block, fp16-pair p (elements 2p,2p+1) is stored at
// pair position p' = (p%4)*4 + p/4 (4x4 transpose, involution). Both operands
// of every GEMM use the same permutation, so dot products are unchanged.
__device__ __half g_xh[(size_t)B_ * T_ * C_];
__device__ __half g_xl[(size_t)B_ * T_ * C_];
__device__ __half g_wqh[(size_t)H_ * C_];
__device__ __half g_wql[(size_t)H_ * C_];
__device__ __half g_wkh[(size_t)H_ * C_];
__device__ __half g_wkl[(size_t)H_ * C_];
__device__ __half g_wvh[(size_t)H_ * C_];
__device__ __half g_wvl[(size_t)H_ * C_];
__device__ __half g_qh[(size_t)B_ * T_ * H_];
__device__ __half g_ql[(size_t)B_ * T_ * H_];
__device__ __half g_kh[(size_t)B_ * T_ * H_];
__device__ __half g_kl[(size_t)B_ * T_ * H_];
__device__ __half g_vth[(size_t)B_ * H_ * T_];   // v transposed: [b][h][t]
__device__ __half g_vtl[(size_t)B_ * H_ * T_];
__device__ __half g_weih[(size_t)B_ * T_ * T_];
__device__ __half g_weil[(size_t)B_ * T_ * T_];

// ---------------- helpers ----------------
__device__ __forceinline__ uint32_t smem_u32(const void* p) {
    uint32_t a;
    asm("{ .reg .u64 t; cvta.to.shared.u64 t, %1; cvt.u32.u64 %0, t; }" : "=r"(a) : "l"(p));
    return a;
}
__device__ __forceinline__ uint32_t pack2(__half a, __half b) {
    __half2 h2 = __halves2half2(a, b);
    return *reinterpret_cast<uint32_t*>(&h2);
}
__device__ __forceinline__ void cpa16(uint32_t dst, const void* src) {
    asm volatile("cp.async.cg.shared.global [%0], [%1], 16;" :: "r"(dst), "l"(src));
}
__device__ __forceinline__ void cp_commit() {
    asm volatile("cp.async.commit_group;" ::: "memory");
}
template <int N>
__device__ __forceinline__ void cp_wait() {
    asm volatile("cp.async.wait_group %0;" :: "n"(N) : "memory");
}
// D += A*B, m16n8k16 fp16 inputs, fp32 accum
__device__ __forceinline__ void mma16(float* d, uint32_t a0, uint32_t a1, uint32_t a2,
                                      uint32_t a3, uint32_t b0, uint32_t b1) {
    asm volatile(
        "mma.sync.aligned.m16n8k16.row.col.f32.f16.f16.f32 "
        "{%0,%1,%2,%3},{%4,%5,%6,%7},{%8,%9},{%0,%1,%2,%3};"
        : "+f"(d[0]), "+f"(d[1]), "+f"(d[2]), "+f"(d[3])
        : "r"(a0), "r"(a1), "r"(a2), "r"(a3), "r"(b0), "r"(b1));
}
// permuted element index within 32-block (pair-level 4x4 transpose; involution)
__device__ __forceinline__ int pperm(int c) {
    const int p = (c & 31) >> 1;
    const int pp = ((p & 3) << 2) | (p >> 2);
    return (c & ~31) | (pp << 1) | (c & 1);
}

// ---------------- FP16x3 NT GEMM via mma.sync (pair-permuted operands) ----------------
// C[m,n] = alpha * sum_k A[m,k]*B[n,k], A=(Ah+Al), B=(Bh+Bl) fp16 pairs.
// CTA 128x128, BK=32, 256 thr (2x4 warps, 64x32 warp tiles).
// SMEM stage: 4 arrays [128][32] halves (8KB each) = 32KB; double buffered.
// EPI=0: Cf = fp32 result*alpha (linear cols). EPI=1: Ch/Cl = fp16 hi/lo, permuted cols.
// PASSES=3: hh + lh + hl. PASSES=2: hh + lh (Bl never touched).
// causal: 0 none; 1 skip block if bn>bm; 2 Keff=min(K,(bm+1)*128), heavy-first bm remap.
static constexpr int GEMM_SMEM = 2 * 32768;   // 64 KB double buffer

template <int EPI, int PASSES>
__global__ __launch_bounds__(256, 2)
void mma_nt(const __half* __restrict__ Ahi, const __half* __restrict__ Alo,
            const __half* __restrict__ Bhi, const __half* __restrict__ Blo,
            float* __restrict__ Cf, __half* __restrict__ Ch, __half* __restrict__ Cl,
            int K, int lda, int ldb, int ldc,
            long long sA, long long sB, long long sC,
            float alpha, int causal)
{
    extern __shared__ char smc[];
    const int bn = blockIdx.x, bz = blockIdx.z;
    int bm = blockIdx.y;
    if (causal == 1 && bn > bm) return;
    if (causal == 2) bm = gridDim.y - 1 - bm;     // heavy tiles first
    int Keff = K;
    if (causal == 2) { int kl = (bm + 1) * 128; Keff = kl < K ? kl : K; }
    const int nk = Keff / 32;

    const __half* Ah = Ahi + (size_t)bz * sA;
    const __half* Al = Alo + (size_t)bz * sA;
    const __half* Bh = Bhi + (size_t)bz * sB;
    const __half* Bl = Blo + (size_t)bz * sB;

    const int tid = threadIdx.x;
    const int lane = tid & 31, w = tid >> 5;
    const int wm = w & 1, wn = w >> 1;            // 2 (M) x 4 (N) warp grid
    const int gr = lane >> 2, tc = lane & 3;
    const uint32_t sbase = smem_u32(smc);

    // stage loader: arrays of [128][32] halves (64B rows); 512 16B-chunks each.
    auto load_stage = [&](int kt, int s) {
        const int k0 = kt * 32;
        const uint32_t dst = sbase + (uint32_t)s * 32768u;
#pragma unroll
        for (int t = 0; t < 2; t++) {
            const int idx = t * 256 + tid;         // 0..511
            const int row = idx >> 2, j = (idx & 3) * 8;
            const uint32_t off = (uint32_t)(row * 64 + j * 2);
            const size_t ga = (size_t)(bm * 128 + row) * lda + k0 + j;
            const size_t gb = (size_t)(bn * 128 + row) * ldb + k0 + j;
            cpa16(dst + off,           Ah + ga);
            cpa16(dst + 8192u + off,   Al + ga);
            cpa16(dst + 16384u + off,  Bh + gb);
            if (PASSES == 3) cpa16(dst + 24576u + off, Bl + gb);
        }
        cp_commit();
    };

    float acc[4][4][4];
#pragma unroll
    for (int i = 0; i < 4; i++)
#pragma unroll
        for (int j = 0; j < 4; j++)
#pragma unroll
            for (int r = 0; r < 4; r++) acc[i][j][r] = 0.f;

    load_stage(0, 0);

    const int rbA = (wm * 64 + gr) * 4 + tc;       // uint4 index of A frag row
    const int rbB = (wn * 32 + gr) * 4 + tc;

    for (int kt = 0; kt < nk; kt++) {
        const int s = kt & 1;
        cp_wait<0>();
        __syncthreads();                            // data(kt) visible; compute(kt-1) done
        if (kt + 1 < nk) load_stage(kt + 1, s ^ 1); // overlaps compute(kt)

        const uint4* S   = (const uint4*)(smc + s * 32768);
        const uint4* pAh = S;
        const uint4* pAl = S + 512;
        const uint4* pBh = S + 1024;
        const uint4* pBl = S + 1536;

        // B hi fragments: one uint4 per fn covers both k16 steps
        uint4 bh0 = pBh[rbB], bh1 = pBh[rbB + 32], bh2 = pBh[rbB + 64], bh3 = pBh[rbB + 96];

#pragma unroll
        for (int fm = 0; fm < 4; fm++) {
            const int ra = rbA + fm * 64;           // fm*16 rows * 4
            uint4 a0 = pAh[ra], a8 = pAh[ra + 32];  // rows gr, gr+8
            uint4 l0 = pAl[ra], l8 = pAl[ra + 32];
#pragma unroll
            for (int fn = 0; fn < 4; fn++) {
                const uint4 bh = fn == 0 ? bh0 : fn == 1 ? bh1 : fn == 2 ? bh2 : bh3;
                float* a = acc[fm][fn];
                mma16(a, a0.x, a8.x, a0.y, a8.y, bh.x, bh.y);   // step0 hh
                mma16(a, l0.x, l8.x, l0.y, l8.y, bh.x, bh.y);   // step0 lh
                mma16(a, a0.z, a8.z, a0.w, a8.w, bh.z, bh.w);   // step1 hh
                mma16(a, l0.z, l8.z, l0.w, l8.w, bh.z, bh.w);   // step1 lh
            }
        }

        if (PASSES == 3) {                          // pass 3: hi*lo
            uint4 bl0 = pBl[rbB], bl1 = pBl[rbB + 32], bl2 = pBl[rbB + 64], bl3 = pBl[rbB + 96];
#pragma unroll
            for (int fm = 0; fm < 4; fm++) {
                const int ra = rbA + fm * 64;
                uint4 a0 = pAh[ra], a8 = pAh[ra + 32];
#pragma unroll
                for (int fn = 0; fn < 4; fn++) {
                    const uint4 bl = fn == 0 ? bl0 : fn == 1 ? bl1 : fn == 2 ? bl2 : bl3;
                    float* a = acc[fm][fn];
                    mma16(a, a0.x, a8.x, a0.y, a8.y, bl.x, bl.y);
                    mma16(a, a0.z, a8.z, a0.w, a8.w, bl.z, bl.w);
                }
            }
        }
    }

    // ---- epilogue ----
#pragma unroll
    for (int fm = 0; fm < 4; fm++) {
        const int r0 = bm * 128 + wm * 64 + fm * 16 + gr;
#pragma unroll
        for (int fn = 0; fn < 4; fn++) {
            const int c0 = bn * 128 + wn * 32 + fn * 8 + 2 * tc;
            const size_t b0 = (size_t)bz * sC + (size_t)r0 * ldc;
            const size_t b8 = b0 + (size_t)8 * ldc;
            const float* a = acc[fm][fn];
            if (EPI == 0) {
                *(float2*)(Cf + b0 + c0) = make_float2(a[0] * alpha, a[1] * alpha);
                *(float2*)(Cf + b8 + c0) = make_float2(a[2] * alpha, a[3] * alpha);
            } else {
                const int cp = pperm(c0);           // pair stays adjacent under pperm
                __half h0 = __float2half_rn(a[0]), h1 = __float2half_rn(a[1]);
                __half h2 = __float2half_rn(a[2]), h3 = __float2half_rn(a[3]);
                *(__half2*)(Ch + b0 + cp) = __halves2half2(h0, h1);
                *(__half2*)(Ch + b8 + cp) = __halves2half2(h2, h3);
                *(__half2*)(Cl + b0 + cp) = __halves2half2(
                    __float2half_rn(a[0] - __half2float(h0)),
                    __float2half_rn(a[1] - __half2float(h1)));
                *(__half2*)(Cl + b8 + cp) = __halves2half2(
                    __float2half_rn(a[2] - __half2float(h2)),
                    __float2half_rn(a[3] - __half2float(h3)));
            }
        }
    }
}

// ---------------- elementwise fp16 split, writing pair-permuted layout ----------------
// Thread i handles output pair positions 4u..4u+3 (u=i&3) of 32-block (i>>2):
// stored[4u+b] = source pair (4b+u)  (elements 8b+2u, 8b+2u+1).
__global__ void split_kernel(const float* __restrict__ src,
                             __half* __restrict__ hi, __half* __restrict__ lo, int n8)
{
    const int i = blockIdx.x * blockDim.x + threadIdx.x;
    if (i >= n8) return;
    const int u = i & 3;
    const int blk = (i >> 2) * 32;
    uint32_t ho[4], lw[4];
#pragma unroll
    for (int b = 0; b < 4; b++) {
        const float2 v = *(const float2*)(src + blk + 8 * b + 2 * u);
        __half h0 = __float2half_rn(v.x), h1 = __float2half_rn(v.y);
        __half l0 = __float2half_rn(v.x - __half2float(h0));
        __half l1 = __float2half_rn(v.y - __half2float(h1));
        ho[b] = pack2(h0, h1);
        lw[b] = pack2(l0, l1);
    }
    ((uint2*)(hi + blk))[u * 2 + 0] = make_uint2(ho[0], ho[1]);
    ((uint2*)(hi + blk))[u * 2 + 1] = make_uint2(ho[2], ho[3]);
    ((uint2*)(lo + blk))[u * 2 + 0] = make_uint2(lw[0], lw[1]);
    ((uint2*)(lo + blk))[u * 2 + 1] = make_uint2(lw[2], lw[3]);
}

// ---------------- causal softmax (in-place fp32) + fp16 split (permuted cols) ----------------
__global__ void softmax_split_kernel(float* __restrict__ W,
                                     __half* __restrict__ Wh, __half* __restrict__ Wl, int T)
{
    const long long row = blockIdx.x;
    const int t = (int)(row % T);
    float* p   = W  + row * (long long)T;
    __half* ph = Wh + row * (long long)T;
    __half* pl = Wl + row * (long long)T;
    const int n = t + 1;
    const int tid = threadIdx.x;
    const int nthr = blockDim.x;

    __shared__ float red[32];

    float m = -3.4e38f;
    for (int i = tid; i < n; i += nthr) m = fmaxf(m, p[i]);
#pragma unroll
    for (int o = 16; o; o >>= 1) m = fmaxf(m, __shfl_xor_sync(0xffffffffu, m, o));
    if ((tid & 31) == 0) red[tid >> 5] = m;
    __syncthreads();
    if (tid < 32) {
        float mb = (tid < (nthr >> 5)) ? red[tid] : -3.4e38f;
#pragma unroll
        for (int o = 16; o; o >>= 1) mb = fmaxf(mb, __shfl_xor_sync(0xffffffffu, mb, o));
        if (tid == 0) red[0] = mb;
    }
    __syncthreads();
    m = red[0];
    __syncthreads();

    float s = 0.f;
    for (int i = tid; i < n; i += nthr) {
        float e = expf(p[i] - m);
        p[i] = e;
        s += e;
    }
#pragma unroll
    for (int o = 16; o; o >>= 1) s += __shfl_xor_sync(0xffffffffu, s, o);
    if ((tid & 31) == 0) red[tid >> 5] = s;
    __syncthreads();
    if (tid < 32) {
        float sb = (tid < (nthr >> 5)) ? red[tid] : 0.f;
#pragma unroll
        for (int o = 16; o; o >>= 1) sb += __shfl_xor_sync(0xffffffffu, sb, o);
        if (tid == 0) red[0] = sb;
    }
    __syncthreads();
    const float inv = 1.f / red[0];

    for (int i = tid; i < n; i += nthr) {
        const float wv = p[i] * inv;
        p[i] = wv;
        const __half h = __float2half_rn(wv);
        const int ip = pperm(i);
        ph[ip] = h;
        pl[ip] = __float2half_rn(wv - __half2float(h));
    }
    const __half z = __float2half_rn(0.f);
    for (int i = n + tid; i < T; i += nthr) {
        p[i] = 0.f;
        const int ip = pperm(i);
        ph[ip] = z;
        pl[ip] = z;
    }
}

// ---------------- launch ----------------
extern "C" void kernel_launch(void* const* d_in, const int* in_sizes, int n_in,
                              void* d_out, int out_size)
{
    (void)in_sizes; (void)n_in; (void)out_size;
    const float* x  = (const float*)d_in[0];
    const float* Wk = (const float*)d_in[1];
    const float* Wq = (const float*)d_in[2];
    const float* Wv = (const float*)d_in[3];

    float* out = (float*)d_out;                      // [B, T, H]
    float* wei = out + (size_t)B_ * T_ * H_;         // [B, T, T]

    __half *xh, *xl, *wqh, *wql, *wkh, *wkl, *wvh, *wvl;
    __half *qh, *ql, *kh, *kl, *vth, *vtl, *weih, *weil;
    cudaGetSymbolAddress((void**)&xh, g_xh);   cudaGetSymbolAddress((void**)&xl, g_xl);
    cudaGetSymbolAddress((void**)&wqh, g_wqh); cudaGetSymbolAddress((void**)&wql, g_wql);
    cudaGetSymbolAddress((void**)&wkh, g_wkh); cudaGetSymbolAddress((void**)&wkl, g_wkl);
    cudaGetSymbolAddress((void**)&wvh, g_wvh); cudaGetSymbolAddress((void**)&wvl, g_wvl);
    cudaGetSymbolAddress((void**)&qh, g_qh);   cudaGetSymbolAddress((void**)&ql, g_ql);
    cudaGetSymbolAddress((void**)&kh, g_kh);   cudaGetSymbolAddress((void**)&kl, g_kl);
    cudaGetSymbolAddress((void**)&vth, g_vth); cudaGetSymbolAddress((void**)&vtl, g_vtl);
    cudaGetSymbolAddress((void**)&weih, g_weih); cudaGetSymbolAddress((void**)&weil, g_weil);

    cudaFuncSetAttribute(mma_nt<0,3>, cudaFuncAttributeMaxDynamicSharedMemorySize, GEMM_SMEM);
    cudaFuncSetAttribute(mma_nt<1,3>, cudaFuncAttributeMaxDynamicSharedMemorySize, GEMM_SMEM);
    cudaFuncSetAttribute(mma_nt<0,2>, cudaFuncAttributeMaxDynamicSharedMemorySize, GEMM_SMEM);

    // 1) split x and weights to fp16 hi/lo (pair-permuted storage)
    {
        const int n8x = (B_ * T_ * C_) / 8;
        split_kernel<<<(n8x + 255) / 256, 256>>>(x, xh, xl, n8x);
        const int n8w = (H_ * C_) / 8;
        split_kernel<<<(n8w + 255) / 256, 256>>>(Wq, wqh, wql, n8w);
        split_kernel<<<(n8w + 255) / 256, 256>>>(Wk, wkh, wkl, n8w);
        split_kernel<<<(n8w + 255) / 256, 256>>>(Wv, wvh, wvl, n8w);
    }

    const dim3 blk(256);

    // 2) projections (epilogue writes permuted fp16 hi/lo)
    {
        const dim3 g(H_ / 128, (B_ * T_) / 128, 1);
        mma_nt<1,3><<<g, blk, GEMM_SMEM>>>(xh, xl, wqh, wql, nullptr, qh, ql,
                                           C_, C_, C_, H_, 0, 0, 0, 1.f, 0);
        mma_nt<1,3><<<g, blk, GEMM_SMEM>>>(xh, xl, wkh, wkl, nullptr, kh, kl,
                                           C_, C_, C_, H_, 0, 0, 0, 1.f, 0);
    }
    //    vT[b,h,t] = Wv[h,:]·x[b,t,:]
    {
        const dim3 g(T_ / 128, H_ / 128, B_);
        mma_nt<1,3><<<g, blk, GEMM_SMEM>>>(wvh, wvl, xh, xl, nullptr, vth, vtl,
                                           C_, C_, C_, T_,
                                           0, (long long)T_ * C_, (long long)H_ * T_, 1.f, 0);
    }

    // 3) logits: wei[b,t,s] = (1/32) q[b,t,:]·k[b,s,:]  (causal block skip)
    {
        const dim3 g(T_ / 128, T_ / 128, B_);
        mma_nt<0,3><<<g, blk, GEMM_SMEM>>>(qh, ql, kh, kl, wei, nullptr, nullptr,
                                           H_, H_, H_, T_,
                                           (long long)T_ * H_, (long long)T_ * H_,
                                           (long long)T_ * T_, 0.03125f, 1);
    }

    // 4) causal softmax in-place + permuted fp16 hi/lo split of wei
    softmax_split_kernel<<<B_ * T_, 256>>>(wei, weih, weil, T_);

    // 5) out[b,t,h] = sum_s wei[b,t,s] * vT[b,h,s]  (causal K limit, 2-pass, heavy-first)
    {
        const dim3 g(H_ / 128, T_ / 128, B_);
        mma_nt<0,2><<<g, blk, GEMM_SMEM>>>(weih, weil, vth, vtl, out, nullptr, nullptr,
                                           T_, T_, T_, H_,
                                           (long long)T_ * T_, (long long)H_ * T_,
                                           (long long)T_ * H_, 1.f, 2);
    }
}

// round 7
// speedup vs baseline: 3.9141x; 1.1465x over previous
#include <cuda_runtime.h>
#include <cuda_fp16.h>
#include <cstdint>

// ---------------- problem shape ----------------
static constexpr int B_ = 8;
static constexpr int T_ = 2048;
static constexpr int C_ = 1024;
static constexpr int H_ = 1024;

// ---------------- scratch (__device__ globals) ----------------
// fp16 hi/lo arrays, PAIR-PERMUTED along the contraction dim: within each
// 32-element K-block, fp16-pair p (elements 2p,2p+1) sits at pair position
// (p%4)*4 + p/4 (4x4 transpose, involution). Applied to both operands of
// every GEMM, so dot products are unchanged.
__device__ __half g_xh[(size_t)B_ * T_ * C_];
__device__ __half g_xl[(size_t)B_ * T_ * C_];
__device__ __half g_wqh[(size_t)H_ * C_];
__device__ __half g_wql[(size_t)H_ * C_];
__device__ __half g_wkh[(size_t)H_ * C_];
__device__ __half g_wkl[(size_t)H_ * C_];
__device__ __half g_wvh[(size_t)H_ * C_];
__device__ __half g_wvl[(size_t)H_ * C_];
__device__ __half g_qh[(size_t)B_ * T_ * H_];
__device__ __half g_ql[(size_t)B_ * T_ * H_];
__device__ __half g_kh[(size_t)B_ * T_ * H_];
__device__ __half g_kl[(size_t)B_ * T_ * H_];
__device__ __half g_vth[(size_t)B_ * H_ * T_];   // v transposed: [b][h][t], hi only
__device__ __half g_weih[(size_t)B_ * T_ * T_];  // wei fp16 hi only

// ---------------- helpers ----------------
__device__ __forceinline__ uint32_t pack2(__half a, __half b) {
    __half2 h2 = __halves2half2(a, b);
    return *reinterpret_cast<uint32_t*>(&h2);
}
__device__ __forceinline__ void cpa16(uint32_t dst, const void* src) {
    asm volatile("cp.async.cg.shared.global [%0], [%1], 16;" :: "r"(dst), "l"(src));
}
__device__ __forceinline__ void cp_commit() {
    asm volatile("cp.async.commit_group;" ::: "memory");
}
template <int N>
__device__ __forceinline__ void cp_wait() {
    asm volatile("cp.async.wait_group %0;" :: "n"(N) : "memory");
}
__device__ __forceinline__ uint32_t smem_u32(const void* p) {
    uint32_t a;
    asm("{ .reg .u64 t; cvta.to.shared.u64 t, %1; cvt.u32.u64 %0, t; }" : "=r"(a) : "l"(p));
    return a;
}
// D += A*B, m16n8k16 fp16 inputs, fp32 accum
__device__ __forceinline__ void mma16(float* d, uint32_t a0, uint32_t a1, uint32_t a2,
                                      uint32_t a3, uint32_t b0, uint32_t b1) {
    asm volatile(
        "mma.sync.aligned.m16n8k16.row.col.f32.f16.f16.f32 "
        "{%0,%1,%2,%3},{%4,%5,%6,%7},{%8,%9},{%0,%1,%2,%3};"
        : "+f"(d[0]), "+f"(d[1]), "+f"(d[2]), "+f"(d[3])
        : "r"(a0), "r"(a1), "r"(a2), "r"(a3), "r"(b0), "r"(b1));
}
// permuted element index within 32-block (pair-level 4x4 transpose; involution)
__device__ __forceinline__ int pperm(int c) {
    const int p = (c & 31) >> 1;
    const int pp = ((p & 3) << 2) | (p >> 2);
    return (c & ~31) | (pp << 1) | (c & 1);
}

// ---------------- FP16 multi-pass NT GEMM via mma.sync (pair-permuted operands) ----------------
// C[m,n] = alpha * sum_k A[m,k]*B[n,k]. CTA 128x128, BK=32, 256 thr (2x4 warps).
// PASSES=3: AhBh + AlBh + AhBl.  PASSES=2: AhBh + AlBh.  PASSES=1: AhBh only.
// EPI=0: Cf = fp32*alpha (linear cols). EPI=1: Ch/Cl fp16 hi/lo (permuted cols).
// EPI=2: Ch fp16 hi only (permuted cols).
// causal: 0 none; 1 skip block if bn>bm; 2 Keff=min(K,(bm+1)*128), heavy-first bm remap.
static constexpr int GEMM_SMEM = 2 * 32768;   // 64 KB double buffer

template <int EPI, int PASSES>
__global__ __launch_bounds__(256, 2)
void mma_nt(const __half* __restrict__ Ahi, const __half* __restrict__ Alo,
            const __half* __restrict__ Bhi, const __half* __restrict__ Blo,
            float* __restrict__ Cf, __half* __restrict__ Ch, __half* __restrict__ Cl,
            int K, int lda, int ldb, int ldc,
            long long sA, long long sB, long long sC,
            float alpha, int causal)
{
    extern __shared__ char smc[];
    const int bn = blockIdx.x, bz = blockIdx.z;
    int bm = blockIdx.y;
    if (causal == 1 && bn > bm) return;
    if (causal == 2) bm = gridDim.y - 1 - bm;     // heavy tiles first
    int Keff = K;
    if (causal == 2) { int kl = (bm + 1) * 128; Keff = kl < K ? kl : K; }
    const int nk = Keff / 32;

    const __half* Ah = Ahi + (size_t)bz * sA;
    const __half* Al = (PASSES >= 2) ? Alo + (size_t)bz * sA : nullptr;
    const __half* Bh = Bhi + (size_t)bz * sB;
    const __half* Bl = (PASSES == 3) ? Blo + (size_t)bz * sB : nullptr;

    const int tid = threadIdx.x;
    const int lane = tid & 31, w = tid >> 5;
    const int wm = w & 1, wn = w >> 1;            // 2 (M) x 4 (N) warp grid
    const int gr = lane >> 2, tc = lane & 3;
    const uint32_t sbase = smem_u32(smc);

    // stage loader: arrays of [128][32] halves (64B rows); 512 16B-chunks each.
    auto load_stage = [&](int kt, int s) {
        const int k0 = kt * 32;
        const uint32_t dst = sbase + (uint32_t)s * 32768u;
#pragma unroll
        for (int t = 0; t < 2; t++) {
            const int idx = t * 256 + tid;         // 0..511
            const int row = idx >> 2, j = (idx & 3) * 8;
            const uint32_t off = (uint32_t)(row * 64 + j * 2);
            const size_t ga = (size_t)(bm * 128 + row) * lda + k0 + j;
            const size_t gb = (size_t)(bn * 128 + row) * ldb + k0 + j;
            cpa16(dst + off,           Ah + ga);
            if (PASSES >= 2) cpa16(dst + 8192u + off, Al + ga);
            cpa16(dst + 16384u + off,  Bh + gb);
            if (PASSES == 3) cpa16(dst + 24576u + off, Bl + gb);
        }
        cp_commit();
    };

    float acc[4][4][4];
#pragma unroll
    for (int i = 0; i < 4; i++)
#pragma unroll
        for (int j = 0; j < 4; j++)
#pragma unroll
            for (int r = 0; r < 4; r++) acc[i][j][r] = 0.f;

    load_stage(0, 0);

    const int rbA = (wm * 64 + gr) * 4 + tc;       // uint4 index of A frag row
    const int rbB = (wn * 32 + gr) * 4 + tc;

    for (int kt = 0; kt < nk; kt++) {
        const int s = kt & 1;
        cp_wait<0>();
        __syncthreads();                            // data(kt) visible; compute(kt-1) done
        if (kt + 1 < nk) load_stage(kt + 1, s ^ 1); // overlaps compute(kt)

        const uint4* S   = (const uint4*)(smc + s * 32768);
        const uint4* pAh = S;
        const uint4* pAl = S + 512;
        const uint4* pBh = S + 1024;
        const uint4* pBl = S + 1536;

        // B hi fragments: one uint4 per fn covers both k16 steps
        uint4 bh0 = pBh[rbB], bh1 = pBh[rbB + 32], bh2 = pBh[rbB + 64], bh3 = pBh[rbB + 96];

#pragma unroll
        for (int fm = 0; fm < 4; fm++) {
            const int ra = rbA + fm * 64;           // fm*16 rows * 4
            uint4 a0 = pAh[ra], a8 = pAh[ra + 32];  // rows gr, gr+8
            uint4 l0, l8;
            if (PASSES >= 2) { l0 = pAl[ra]; l8 = pAl[ra + 32]; }
#pragma unroll
            for (int fn = 0; fn < 4; fn++) {
                const uint4 bh = fn == 0 ? bh0 : fn == 1 ? bh1 : fn == 2 ? bh2 : bh3;
                float* a = acc[fm][fn];
                mma16(a, a0.x, a8.x, a0.y, a8.y, bh.x, bh.y);       // step0 hh
                if (PASSES >= 2) mma16(a, l0.x, l8.x, l0.y, l8.y, bh.x, bh.y);
                mma16(a, a0.z, a8.z, a0.w, a8.w, bh.z, bh.w);       // step1 hh
                if (PASSES >= 2) mma16(a, l0.z, l8.z, l0.w, l8.w, bh.z, bh.w);
            }
        }

        if (PASSES == 3) {                          // pass 3: hi*lo
            uint4 bl0 = pBl[rbB], bl1 = pBl[rbB + 32], bl2 = pBl[rbB + 64], bl3 = pBl[rbB + 96];
#pragma unroll
            for (int fm = 0; fm < 4; fm++) {
                const int ra = rbA + fm * 64;
                uint4 a0 = pAh[ra], a8 = pAh[ra + 32];
#pragma unroll
                for (int fn = 0; fn < 4; fn++) {
                    const uint4 bl = fn == 0 ? bl0 : fn == 1 ? bl1 : fn == 2 ? bl2 : bl3;
                    float* a = acc[fm][fn];
                    mma16(a, a0.x, a8.x, a0.y, a8.y, bl.x, bl.y);
                    mma16(a, a0.z, a8.z, a0.w, a8.w, bl.z, bl.w);
                }
            }
        }
    }

    // ---- epilogue ----
#pragma unroll
    for (int fm = 0; fm < 4; fm++) {
        const int r0 = bm * 128 + wm * 64 + fm * 16 + gr;
#pragma unroll
        for (int fn = 0; fn < 4; fn++) {
            const int c0 = bn * 128 + wn * 32 + fn * 8 + 2 * tc;
            const size_t b0 = (size_t)bz * sC + (size_t)r0 * ldc;
            const size_t b8 = b0 + (size_t)8 * ldc;
            const float* a = acc[fm][fn];
            if (EPI == 0) {
                *(float2*)(Cf + b0 + c0) = make_float2(a[0] * alpha, a[1] * alpha);
                *(float2*)(Cf + b8 + c0) = make_float2(a[2] * alpha, a[3] * alpha);
            } else {
                const int cp = pperm(c0);           // pair stays adjacent under pperm
                __half h0 = __float2half_rn(a[0]), h1 = __float2half_rn(a[1]);
                __half h2 = __float2half_rn(a[2]), h3 = __float2half_rn(a[3]);
                *(__half2*)(Ch + b0 + cp) = __halves2half2(h0, h1);
                *(__half2*)(Ch + b8 + cp) = __halves2half2(h2, h3);
                if (EPI == 1) {
                    *(__half2*)(Cl + b0 + cp) = __halves2half2(
                        __float2half_rn(a[0] - __half2float(h0)),
                        __float2half_rn(a[1] - __half2float(h1)));
                    *(__half2*)(Cl + b8 + cp) = __halves2half2(
                        __float2half_rn(a[2] - __half2float(h2)),
                        __float2half_rn(a[3] - __half2float(h3)));
                }
            }
        }
    }
}

// ---------------- elementwise fp16 split, writing pair-permuted layout ----------------
__global__ void split_kernel(const float* __restrict__ src,
                             __half* __restrict__ hi, __half* __restrict__ lo, int n8)
{
    const int i = blockIdx.x * blockDim.x + threadIdx.x;
    if (i >= n8) return;
    const int u = i & 3;
    const int blk = (i >> 2) * 32;
    uint32_t ho[4], lw[4];
#pragma unroll
    for (int b = 0; b < 4; b++) {
        const float2 v = *(const float2*)(src + blk + 8 * b + 2 * u);
        __half h0 = __float2half_rn(v.x), h1 = __float2half_rn(v.y);
        __half l0 = __float2half_rn(v.x - __half2float(h0));
        __half l1 = __float2half_rn(v.y - __half2float(h1));
        ho[b] = pack2(h0, h1);
        lw[b] = pack2(l0, l1);
    }
    ((uint2*)(hi + blk))[u * 2 + 0] = make_uint2(ho[0], ho[1]);
    ((uint2*)(hi + blk))[u * 2 + 1] = make_uint2(ho[2], ho[3]);
    ((uint2*)(lo + blk))[u * 2 + 0] = make_uint2(lw[0], lw[1]);
    ((uint2*)(lo + blk))[u * 2 + 1] = make_uint2(lw[2], lw[3]);
}

// ---------------- causal softmax (in-place fp32) + fp16 hi write (permuted cols) ----------------
__global__ void softmax_split_kernel(float* __restrict__ W,
                                     __half* __restrict__ Wh, int T)
{
    const long long row = blockIdx.x;
    const int t = (int)(row % T);
    float* p   = W  + row * (long long)T;
    __half* ph = Wh + row * (long long)T;
    const int n = t + 1;
    const int tid = threadIdx.x;
    const int nthr = blockDim.x;

    __shared__ float red[32];

    float m = -3.4e38f;
    for (int i = tid; i < n; i += nthr) m = fmaxf(m, p[i]);
#pragma unroll
    for (int o = 16; o; o >>= 1) m = fmaxf(m, __shfl_xor_sync(0xffffffffu, m, o));
    if ((tid & 31) == 0) red[tid >> 5] = m;
    __syncthreads();
    if (tid < 32) {
        float mb = (tid < (nthr >> 5)) ? red[tid] : -3.4e38f;
#pragma unroll
        for (int o = 16; o; o >>= 1) mb = fmaxf(mb, __shfl_xor_sync(0xffffffffu, mb, o));
        if (tid == 0) red[0] = mb;
    }
    __syncthreads();
    m = red[0];
    __syncthreads();

    float s = 0.f;
    for (int i = tid; i < n; i += nthr) {
        float e = expf(p[i] - m);
        p[i] = e;
        s += e;
    }
#pragma unroll
    for (int o = 16; o; o >>= 1) s += __shfl_xor_sync(0xffffffffu, s, o);
    if ((tid & 31) == 0) red[tid >> 5] = s;
    __syncthreads();
    if (tid < 32) {
        float sb = (tid < (nthr >> 5)) ? red[tid] : 0.f;
#pragma unroll
        for (int o = 16; o; o >>= 1) sb += __shfl_xor_sync(0xffffffffu, sb, o);
        if (tid == 0) red[0] = sb;
    }
    __syncthreads();
    const float inv = 1.f / red[0];

    for (int i = tid; i < n; i += nthr) {
        const float wv = p[i] * inv;
        p[i] = wv;
        ph[pperm(i)] = __float2half_rn(wv);
    }
    const __half z = __float2half_rn(0.f);
    for (int i = n + tid; i < T; i += nthr) {
        p[i] = 0.f;
        ph[pperm(i)] = z;
    }
}

// ---------------- launch ----------------
extern "C" void kernel_launch(void* const* d_in, const int* in_sizes, int n_in,
                              void* d_out, int out_size)
{
    (void)in_sizes; (void)n_in; (void)out_size;
    const float* x  = (const float*)d_in[0];
    const float* Wk = (const float*)d_in[1];
    const float* Wq = (const float*)d_in[2];
    const float* Wv = (const float*)d_in[3];

    float* out = (float*)d_out;                      // [B, T, H]
    float* wei = out + (size_t)B_ * T_ * H_;         // [B, T, T]

    __half *xh, *xl, *wqh, *wql, *wkh, *wkl, *wvh, *wvl;
    __half *qh, *ql, *kh, *kl, *vth, *weih;
    cudaGetSymbolAddress((void**)&xh, g_xh);   cudaGetSymbolAddress((void**)&xl, g_xl);
    cudaGetSymbolAddress((void**)&wqh, g_wqh); cudaGetSymbolAddress((void**)&wql, g_wql);
    cudaGetSymbolAddress((void**)&wkh, g_wkh); cudaGetSymbolAddress((void**)&wkl, g_wkl);
    cudaGetSymbolAddress((void**)&wvh, g_wvh); cudaGetSymbolAddress((void**)&wvl, g_wvl);
    cudaGetSymbolAddress((void**)&qh, g_qh);   cudaGetSymbolAddress((void**)&ql, g_ql);
    cudaGetSymbolAddress((void**)&kh, g_kh);   cudaGetSymbolAddress((void**)&kl, g_kl);
    cudaGetSymbolAddress((void**)&vth, g_vth);
    cudaGetSymbolAddress((void**)&weih, g_weih);

    cudaFuncSetAttribute(mma_nt<0,3>, cudaFuncAttributeMaxDynamicSharedMemorySize, GEMM_SMEM);
    cudaFuncSetAttribute(mma_nt<1,3>, cudaFuncAttributeMaxDynamicSharedMemorySize, GEMM_SMEM);
    cudaFuncSetAttribute(mma_nt<2,2>, cudaFuncAttributeMaxDynamicSharedMemorySize, GEMM_SMEM);
    cudaFuncSetAttribute(mma_nt<0,1>, cudaFuncAttributeMaxDynamicSharedMemorySize, GEMM_SMEM);

    // 1) split x and weights to fp16 hi/lo (pair-permuted storage)
    {
        const int n8x = (B_ * T_ * C_) / 8;
        split_kernel<<<(n8x + 255) / 256, 256>>>(x, xh, xl, n8x);
        const int n8w = (H_ * C_) / 8;
        split_kernel<<<(n8w + 255) / 256, 256>>>(Wq, wqh, wql, n8w);
        split_kernel<<<(n8w + 255) / 256, 256>>>(Wk, wkh, wkl, n8w);
        split_kernel<<<(n8w + 255) / 256, 256>>>(Wv, wvh, wvl, n8w);
    }

    const dim3 blk(256);

    // 2) q,k projections: 3-pass, epilogue writes permuted fp16 hi/lo
    {
        const dim3 g(H_ / 128, (B_ * T_) / 128, 1);
        mma_nt<1,3><<<g, blk, GEMM_SMEM>>>(xh, xl, wqh, wql, nullptr, qh, ql,
                                           C_, C_, C_, H_, 0, 0, 0, 1.f, 0);
        mma_nt<1,3><<<g, blk, GEMM_SMEM>>>(xh, xl, wkh, wkl, nullptr, kh, kl,
                                           C_, C_, C_, H_, 0, 0, 0, 1.f, 0);
    }
    //    v: vT[b,h,t] = Wv[h,:]·x[b,t,:], 2-pass (hh + Wv_lo·x_hi), hi-only output
    {
        const dim3 g(T_ / 128, H_ / 128, B_);
        mma_nt<2,2><<<g, blk, GEMM_SMEM>>>(wvh, wvl, xh, xl, nullptr, vth, nullptr,
                                           C_, C_, C_, T_,
                                           0, (long long)T_ * C_, (long long)H_ * T_, 1.f, 0);
    }

    // 3) logits: wei[b,t,s] = (1/32) q[b,t,:]·k[b,s,:]  (3-pass, causal block skip)
    {
        const dim3 g(T_ / 128, T_ / 128, B_);
        mma_nt<0,3><<<g, blk, GEMM_SMEM>>>(qh, ql, kh, kl, wei, nullptr, nullptr,
                                           H_, H_, H_, T_,
                                           (long long)T_ * H_, (long long)T_ * H_,
                                           (long long)T_ * T_, 0.03125f, 1);
    }

    // 4) causal softmax in-place + permuted fp16 hi of wei
    softmax_split_kernel<<<B_ * T_, 256>>>(wei, weih, T_);

    // 5) out[b,t,h] = sum_s wei_h[b,t,s] * vT_h[b,h,s]  (1-pass, causal K, heavy-first)
    {
        const dim3 g(H_ / 128, T_ / 128, B_);
        mma_nt<0,1><<<g, blk, GEMM_SMEM>>>(weih, nullptr, vth, nullptr, out, nullptr, nullptr,
                                           T_, T_, T_, H_,
                                           (long long)T_ * T_, (long long)H_ * T_,
                                           (long long)T_ * H_, 1.f, 2);
    }
}

// round 8
// speedup vs baseline: 4.2662x; 1.0899x over previous
#include <cuda_runtime.h>
#include <cuda_fp16.h>
#include <cstdint>

// ---------------- problem shape ----------------
static constexpr int B_ = 8;
static constexpr int T_ = 2048;
static constexpr int C_ = 1024;
static constexpr int H_ = 1024;

// ---------------- scratch (__device__ globals) ----------------
// fp16 hi/lo arrays, PAIR-PERMUTED along the contraction dim: within each
// 32-element K-block, fp16-pair p (elements 2p,2p+1) sits at pair position
// (p%4)*4 + p/4 (4x4 transpose, involution). Applied to both operands of
// every GEMM, so dot products are unchanged.
__device__ __half g_xh[(size_t)B_ * T_ * C_];
__device__ __half g_xl[(size_t)B_ * T_ * C_];
__device__ __half g_wqh[(size_t)H_ * C_];
__device__ __half g_wql[(size_t)H_ * C_];
__device__ __half g_wkh[(size_t)H_ * C_];
__device__ __half g_wkl[(size_t)H_ * C_];
__device__ __half g_wvh[(size_t)H_ * C_];
__device__ __half g_qh[(size_t)B_ * T_ * H_];
__device__ __half g_ql[(size_t)B_ * T_ * H_];
__device__ __half g_kh[(size_t)B_ * T_ * H_];
__device__ __half g_kl[(size_t)B_ * T_ * H_];
__device__ __half g_vth[(size_t)B_ * H_ * T_];   // v transposed: [b][h][t], hi only
__device__ __half g_weih[(size_t)B_ * T_ * T_];  // wei fp16 hi only

// ---------------- helpers ----------------
__device__ __forceinline__ uint32_t pack2(__half a, __half b) {
    __half2 h2 = __halves2half2(a, b);
    return *reinterpret_cast<uint32_t*>(&h2);
}
__device__ __forceinline__ void cpa16(uint32_t dst, const void* src) {
    asm volatile("cp.async.cg.shared.global [%0], [%1], 16;" :: "r"(dst), "l"(src));
}
__device__ __forceinline__ void cp_commit() {
    asm volatile("cp.async.commit_group;" ::: "memory");
}
template <int N>
__device__ __forceinline__ void cp_wait() {
    asm volatile("cp.async.wait_group %0;" :: "n"(N) : "memory");
}
__device__ __forceinline__ uint32_t smem_u32(const void* p) {
    uint32_t a;
    asm("{ .reg .u64 t; cvta.to.shared.u64 t, %1; cvt.u32.u64 %0, t; }" : "=r"(a) : "l"(p));
    return a;
}
// D += A*B, m16n8k16 fp16 inputs, fp32 accum
__device__ __forceinline__ void mma16(float* d, uint32_t a0, uint32_t a1, uint32_t a2,
                                      uint32_t a3, uint32_t b0, uint32_t b1) {
    asm volatile(
        "mma.sync.aligned.m16n8k16.row.col.f32.f16.f16.f32 "
        "{%0,%1,%2,%3},{%4,%5,%6,%7},{%8,%9},{%0,%1,%2,%3};"
        : "+f"(d[0]), "+f"(d[1]), "+f"(d[2]), "+f"(d[3])
        : "r"(a0), "r"(a1), "r"(a2), "r"(a3), "r"(b0), "r"(b1));
}
// permuted element index within 32-block (pair-level 4x4 transpose; involution)
__device__ __forceinline__ int pperm(int c) {
    const int p = (c & 31) >> 1;
    const int pp = ((p & 3) << 2) | (p >> 2);
    return (c & ~31) | (pp << 1) | (c & 1);
}

// ---------------- FP16 multi-pass NT GEMM via mma.sync (pair-permuted operands) ----------------
// C[m,n] = alpha * sum_k A[m,k]*B[n,k]. CTA 128x128, BK=32, 256 thr (2x4 warps).
// PASSES=3: AhBh + AlBh + AhBl.  PASSES=2: AhBh + AlBh.  PASSES=1: AhBh only.
// EPI=0: Cf = fp32*alpha (linear cols). EPI=1: Ch/Cl fp16 hi/lo (permuted cols).
// EPI=2: Ch fp16 hi only (permuted cols).
// causal: 0 none; 1 skip block if bn>bm; 2 Keff=min(K,(bm+1)*128), heavy-first bm remap.
static constexpr int GEMM_SMEM = 2 * 32768;   // 64 KB double buffer

template <int EPI, int PASSES>
__global__ __launch_bounds__(256, 2)
void mma_nt(const __half* __restrict__ Ahi, const __half* __restrict__ Alo,
            const __half* __restrict__ Bhi, const __half* __restrict__ Blo,
            float* __restrict__ Cf, __half* __restrict__ Ch, __half* __restrict__ Cl,
            int K, int lda, int ldb, int ldc,
            long long sA, long long sB, long long sC,
            float alpha, int causal)
{
    extern __shared__ char smc[];
    const int bn = blockIdx.x, bz = blockIdx.z;
    int bm = blockIdx.y;
    if (causal == 1 && bn > bm) return;
    if (causal == 2) bm = gridDim.y - 1 - bm;     // heavy tiles first
    int Keff = K;
    if (causal == 2) { int kl = (bm + 1) * 128; Keff = kl < K ? kl : K; }
    const int nk = Keff / 32;

    const __half* Ah = Ahi + (size_t)bz * sA;
    const __half* Al = (PASSES >= 2) ? Alo + (size_t)bz * sA : nullptr;
    const __half* Bh = Bhi + (size_t)bz * sB;
    const __half* Bl = (PASSES == 3) ? Blo + (size_t)bz * sB : nullptr;

    const int tid = threadIdx.x;
    const int lane = tid & 31, w = tid >> 5;
    const int wm = w & 1, wn = w >> 1;            // 2 (M) x 4 (N) warp grid
    const int gr = lane >> 2, tc = lane & 3;
    const uint32_t sbase = smem_u32(smc);

    // stage loader: arrays of [128][32] halves (64B rows); 512 16B-chunks each.
    auto load_stage = [&](int kt, int s) {
        const int k0 = kt * 32;
        const uint32_t dst = sbase + (uint32_t)s * 32768u;
#pragma unroll
        for (int t = 0; t < 2; t++) {
            const int idx = t * 256 + tid;         // 0..511
            const int row = idx >> 2, j = (idx & 3) * 8;
            const uint32_t off = (uint32_t)(row * 64 + j * 2);
            const size_t ga = (size_t)(bm * 128 + row) * lda + k0 + j;
            const size_t gb = (size_t)(bn * 128 + row) * ldb + k0 + j;
            cpa16(dst + off,           Ah + ga);
            if (PASSES >= 2) cpa16(dst + 8192u + off, Al + ga);
            cpa16(dst + 16384u + off,  Bh + gb);
            if (PASSES == 3) cpa16(dst + 24576u + off, Bl + gb);
        }
        cp_commit();
    };

    float acc[4][4][4];
#pragma unroll
    for (int i = 0; i < 4; i++)
#pragma unroll
        for (int j = 0; j < 4; j++)
#pragma unroll
            for (int r = 0; r < 4; r++) acc[i][j][r] = 0.f;

    load_stage(0, 0);

    const int rbA = (wm * 64 + gr) * 4 + tc;       // uint4 index of A frag row
    const int rbB = (wn * 32 + gr) * 4 + tc;

    for (int kt = 0; kt < nk; kt++) {
        const int s = kt & 1;
        cp_wait<0>();
        __syncthreads();                            // data(kt) visible; compute(kt-1) done
        if (kt + 1 < nk) load_stage(kt + 1, s ^ 1); // overlaps compute(kt)

        const uint4* S   = (const uint4*)(smc + s * 32768);
        const uint4* pAh = S;
        const uint4* pAl = S + 512;
        const uint4* pBh = S + 1024;
        const uint4* pBl = S + 1536;

        // B hi fragments: one uint4 per fn covers both k16 steps
        uint4 bh0 = pBh[rbB], bh1 = pBh[rbB + 32], bh2 = pBh[rbB + 64], bh3 = pBh[rbB + 96];

#pragma unroll
        for (int fm = 0; fm < 4; fm++) {
            const int ra = rbA + fm * 64;           // fm*16 rows * 4
            uint4 a0 = pAh[ra], a8 = pAh[ra + 32];  // rows gr, gr+8
            uint4 l0, l8;
            if (PASSES >= 2) { l0 = pAl[ra]; l8 = pAl[ra + 32]; }
#pragma unroll
            for (int fn = 0; fn < 4; fn++) {
                const uint4 bh = fn == 0 ? bh0 : fn == 1 ? bh1 : fn == 2 ? bh2 : bh3;
                float* a = acc[fm][fn];
                mma16(a, a0.x, a8.x, a0.y, a8.y, bh.x, bh.y);       // step0 hh
                if (PASSES >= 2) mma16(a, l0.x, l8.x, l0.y, l8.y, bh.x, bh.y);
                mma16(a, a0.z, a8.z, a0.w, a8.w, bh.z, bh.w);       // step1 hh
                if (PASSES >= 2) mma16(a, l0.z, l8.z, l0.w, l8.w, bh.z, bh.w);
            }
        }

        if (PASSES == 3) {                          // pass 3: hi*lo
            uint4 bl0 = pBl[rbB], bl1 = pBl[rbB + 32], bl2 = pBl[rbB + 64], bl3 = pBl[rbB + 96];
#pragma unroll
            for (int fm = 0; fm < 4; fm++) {
                const int ra = rbA + fm * 64;
                uint4 a0 = pAh[ra], a8 = pAh[ra + 32];
#pragma unroll
                for (int fn = 0; fn < 4; fn++) {
                    const uint4 bl = fn == 0 ? bl0 : fn == 1 ? bl1 : fn == 2 ? bl2 : bl3;
                    float* a = acc[fm][fn];
                    mma16(a, a0.x, a8.x, a0.y, a8.y, bl.x, bl.y);
                    mma16(a, a0.z, a8.z, a0.w, a8.w, bl.z, bl.w);
                }
            }
        }
    }

    // ---- epilogue ----
#pragma unroll
    for (int fm = 0; fm < 4; fm++) {
        const int r0 = bm * 128 + wm * 64 + fm * 16 + gr;
#pragma unroll
        for (int fn = 0; fn < 4; fn++) {
            const int c0 = bn * 128 + wn * 32 + fn * 8 + 2 * tc;
            const size_t b0 = (size_t)bz * sC + (size_t)r0 * ldc;
            const size_t b8 = b0 + (size_t)8 * ldc;
            const float* a = acc[fm][fn];
            if (EPI == 0) {
                *(float2*)(Cf + b0 + c0) = make_float2(a[0] * alpha, a[1] * alpha);
                *(float2*)(Cf + b8 + c0) = make_float2(a[2] * alpha, a[3] * alpha);
            } else {
                const int cp = pperm(c0);           // pair stays adjacent under pperm
                __half h0 = __float2half_rn(a[0]), h1 = __float2half_rn(a[1]);
                __half h2 = __float2half_rn(a[2]), h3 = __float2half_rn(a[3]);
                *(__half2*)(Ch + b0 + cp) = __halves2half2(h0, h1);
                *(__half2*)(Ch + b8 + cp) = __halves2half2(h2, h3);
                if (EPI == 1) {
                    *(__half2*)(Cl + b0 + cp) = __halves2half2(
                        __float2half_rn(a[0] - __half2float(h0)),
                        __float2half_rn(a[1] - __half2float(h1)));
                    *(__half2*)(Cl + b8 + cp) = __halves2half2(
                        __float2half_rn(a[2] - __half2float(h2)),
                        __float2half_rn(a[3] - __half2float(h3)));
                }
            }
        }
    }
}

// ---------------- elementwise fp16 split, writing pair-permuted layout ----------------
__global__ void split_kernel(const float* __restrict__ src,
                             __half* __restrict__ hi, __half* __restrict__ lo, int n8)
{
    const int i = blockIdx.x * blockDim.x + threadIdx.x;
    if (i >= n8) return;
    const int u = i & 3;
    const int blk = (i >> 2) * 32;
    uint32_t ho[4], lw[4];
#pragma unroll
    for (int b = 0; b < 4; b++) {
        const float2 v = *(const float2*)(src + blk + 8 * b + 2 * u);
        __half h0 = __float2half_rn(v.x), h1 = __float2half_rn(v.y);
        __half l0 = __float2half_rn(v.x - __half2float(h0));
        __half l1 = __float2half_rn(v.y - __half2float(h1));
        ho[b] = pack2(h0, h1);
        lw[b] = pack2(l0, l1);
    }
    ((uint2*)(hi + blk))[u * 2 + 0] = make_uint2(ho[0], ho[1]);
    ((uint2*)(hi + blk))[u * 2 + 1] = make_uint2(ho[2], ho[3]);
    if (lo) {
        ((uint2*)(lo + blk))[u * 2 + 0] = make_uint2(lw[0], lw[1]);
        ((uint2*)(lo + blk))[u * 2 + 1] = make_uint2(lw[2], lw[3]);
    }
}

// ---------------- single-sweep causal softmax + fp16 hi write (permuted cols) ----------------
// One block per row (T=2048, 256 threads, 8 elems/thread in registers).
__global__ __launch_bounds__(256)
void softmax_split_kernel(float* __restrict__ W, __half* __restrict__ Wh, int T)
{
    const long long row = blockIdx.x;
    const int t = (int)(row % T);
    float* p   = W  + row * (long long)T;
    __half* ph = Wh + row * (long long)T;
    const int n = t + 1;
    const int tid = threadIdx.x;
    const int base = tid * 8;

    __shared__ float red[8];

    // load 8 elements (masked: beyond n -> -inf sentinel)
    float v[8];
    {
        float4 a = *(const float4*)(p + base);
        float4 b = *(const float4*)(p + base + 4);
        v[0] = a.x; v[1] = a.y; v[2] = a.z; v[3] = a.w;
        v[4] = b.x; v[5] = b.y; v[6] = b.z; v[7] = b.w;
    }
#pragma unroll
    for (int j = 0; j < 8; j++)
        if (base + j >= n) v[j] = -3.4e38f;

    // block max
    float m = v[0];
#pragma unroll
    for (int j = 1; j < 8; j++) m = fmaxf(m, v[j]);
#pragma unroll
    for (int o = 16; o; o >>= 1) m = fmaxf(m, __shfl_xor_sync(0xffffffffu, m, o));
    if ((tid & 31) == 0) red[tid >> 5] = m;
    __syncthreads();
    if (tid < 32) {
        float mb = (tid < 8) ? red[tid] : -3.4e38f;
#pragma unroll
        for (int o = 4; o; o >>= 1) mb = fmaxf(mb, __shfl_xor_sync(0xffffffffu, mb, o));
        if (tid == 0) red[0] = mb;
    }
    __syncthreads();
    m = red[0];
    __syncthreads();

    // exp + block sum (masked entries -> exact 0)
    float s = 0.f;
#pragma unroll
    for (int j = 0; j < 8; j++) {
        v[j] = (base + j < n) ? expf(v[j] - m) : 0.f;
        s += v[j];
    }
#pragma unroll
    for (int o = 16; o; o >>= 1) s += __shfl_xor_sync(0xffffffffu, s, o);
    if ((tid & 31) == 0) red[tid >> 5] = s;
    __syncthreads();
    if (tid < 32) {
        float sb = (tid < 8) ? red[tid] : 0.f;
#pragma unroll
        for (int o = 4; o; o >>= 1) sb += __shfl_xor_sync(0xffffffffu, sb, o);
        if (tid == 0) red[0] = sb;
    }
    __syncthreads();
    const float inv = 1.f / red[0];

    // normalize, write fp32 wei (zero-filled tail included) + permuted fp16 hi
#pragma unroll
    for (int j = 0; j < 8; j++) v[j] *= inv;
    *(float4*)(p + base)     = make_float4(v[0], v[1], v[2], v[3]);
    *(float4*)(p + base + 4) = make_float4(v[4], v[5], v[6], v[7]);

    // fp16 pair-permuted scatter: thread's 4 pairs land at pair slots
    // {u, 4+u, 8+u, 12+u} of the 32-block, u = tid & 3.
    const int u = tid & 3;
    __half* phb = ph + (base & ~31);
#pragma unroll
    for (int b = 0; b < 4; b++) {
        *(__half2*)(phb + (b * 4 + u) * 2) =
            __halves2half2(__float2half_rn(v[2 * b]), __float2half_rn(v[2 * b + 1]));
    }
}

// ---------------- launch ----------------
extern "C" void kernel_launch(void* const* d_in, const int* in_sizes, int n_in,
                              void* d_out, int out_size)
{
    (void)in_sizes; (void)n_in; (void)out_size;
    const float* x  = (const float*)d_in[0];
    const float* Wk = (const float*)d_in[1];
    const float* Wq = (const float*)d_in[2];
    const float* Wv = (const float*)d_in[3];

    float* out = (float*)d_out;                      // [B, T, H]
    float* wei = out + (size_t)B_ * T_ * H_;         // [B, T, T]

    __half *xh, *xl, *wqh, *wql, *wkh, *wkl, *wvh;
    __half *qh, *ql, *kh, *kl, *vth, *weih;
    cudaGetSymbolAddress((void**)&xh, g_xh);   cudaGetSymbolAddress((void**)&xl, g_xl);
    cudaGetSymbolAddress((void**)&wqh, g_wqh); cudaGetSymbolAddress((void**)&wql, g_wql);
    cudaGetSymbolAddress((void**)&wkh, g_wkh); cudaGetSymbolAddress((void**)&wkl, g_wkl);
    cudaGetSymbolAddress((void**)&wvh, g_wvh);
    cudaGetSymbolAddress((void**)&qh, g_qh);   cudaGetSymbolAddress((void**)&ql, g_ql);
    cudaGetSymbolAddress((void**)&kh, g_kh);   cudaGetSymbolAddress((void**)&kl, g_kl);
    cudaGetSymbolAddress((void**)&vth, g_vth);
    cudaGetSymbolAddress((void**)&weih, g_weih);

    cudaFuncSetAttribute(mma_nt<0,3>, cudaFuncAttributeMaxDynamicSharedMemorySize, GEMM_SMEM);
    cudaFuncSetAttribute(mma_nt<1,3>, cudaFuncAttributeMaxDynamicSharedMemorySize, GEMM_SMEM);
    cudaFuncSetAttribute(mma_nt<2,1>, cudaFuncAttributeMaxDynamicSharedMemorySize, GEMM_SMEM);
    cudaFuncSetAttribute(mma_nt<0,1>, cudaFuncAttributeMaxDynamicSharedMemorySize, GEMM_SMEM);

    // 1) split x and weights to fp16 hi/lo (pair-permuted storage)
    {
        const int n8x = (B_ * T_ * C_) / 8;
        split_kernel<<<(n8x + 255) / 256, 256>>>(x, xh, xl, n8x);
        const int n8w = (H_ * C_) / 8;
        split_kernel<<<(n8w + 255) / 256, 256>>>(Wq, wqh, wql, n8w);
        split_kernel<<<(n8w + 255) / 256, 256>>>(Wk, wkh, wkl, n8w);
        split_kernel<<<(n8w + 255) / 256, 256>>>(Wv, wvh, nullptr, n8w);
    }

    const dim3 blk(256);

    // 2) q,k projections: 3-pass, epilogue writes permuted fp16 hi/lo
    {
        const dim3 g(H_ / 128, (B_ * T_) / 128, 1);
        mma_nt<1,3><<<g, blk, GEMM_SMEM>>>(xh, xl, wqh, wql, nullptr, qh, ql,
                                           C_, C_, C_, H_, 0, 0, 0, 1.f, 0);
        mma_nt<1,3><<<g, blk, GEMM_SMEM>>>(xh, xl, wkh, wkl, nullptr, kh, kl,
                                           C_, C_, C_, H_, 0, 0, 0, 1.f, 0);
    }
    //    v: vT[b,h,t] = Wv_h[h,:]·x_h[b,t,:], 1-pass, hi-only output
    {
        const dim3 g(T_ / 128, H_ / 128, B_);
        mma_nt<2,1><<<g, blk, GEMM_SMEM>>>(wvh, nullptr, xh, nullptr, nullptr, vth, nullptr,
                                           C_, C_, C_, T_,
                                           0, (long long)T_ * C_, (long long)H_ * T_, 1.f, 0);
    }

    // 3) logits: wei[b,t,s] = (1/32) q[b,t,:]·k[b,s,:]  (3-pass, causal block skip)
    {
        const dim3 g(T_ / 128, T_ / 128, B_);
        mma_nt<0,3><<<g, blk, GEMM_SMEM>>>(qh, ql, kh, kl, wei, nullptr, nullptr,
                                           H_, H_, H_, T_,
                                           (long long)T_ * H_, (long long)T_ * H_,
                                           (long long)T_ * T_, 0.03125f, 1);
    }

    // 4) single-sweep causal softmax + permuted fp16 hi of wei
    softmax_split_kernel<<<B_ * T_, 256>>>(wei, weih, T_);

    // 5) out[b,t,h] = sum_s wei_h[b,t,s] * vT_h[b,h,s]  (1-pass, causal K, heavy-first)
    {
        const dim3 g(H_ / 128, T_ / 128, B_);
        mma_nt<0,1><<<g, blk, GEMM_SMEM>>>(weih, nullptr, vth, nullptr, out, nullptr, nullptr,
                                           T_, T_, T_, H_,
                                           (long long)T_ * T_, (long long)H_ * T_,
                                           (long long)T_ * H_, 1.f, 2);
    }
}

// round 9
// speedup vs baseline: 5.2980x; 1.2418x over previous
#include <cuda_runtime.h>
#include <cuda_fp16.h>
#include <cstdint>

// ---------------- problem shape ----------------
static constexpr int B_ = 8;
static constexpr int T_ = 2048;
static constexpr int C_ = 1024;
static constexpr int H_ = 1024;

// ---------------- scratch (__device__ globals) ----------------
// fp16 hi/lo arrays, PAIR-PERMUTED along the contraction dim: within each
// 32-element K-block, fp16-pair p (elements 2p,2p+1) sits at pair position
// (p%4)*4 + p/4 (4x4 transpose, involution). Applied to both operands of
// every GEMM, so dot products are unchanged.
__device__ __half g_xh[(size_t)B_ * T_ * C_];
__device__ __half g_xl[(size_t)B_ * T_ * C_];
__device__ __half g_wqth[(size_t)C_ * H_];   // Wq^T [C,H], permuted along H
__device__ __half g_wqtl[(size_t)C_ * H_];
__device__ __half g_wkth[(size_t)C_ * H_];   // Wk^T [C,H], permuted along H
__device__ __half g_wktl[(size_t)C_ * H_];
__device__ __half g_mth[(size_t)C_ * C_];    // Mt[c'][c] = (Wq^T Wk)[c][c'], permuted along c
__device__ __half g_mtl[(size_t)C_ * C_];
__device__ __half g_uh[(size_t)B_ * T_ * C_];  // u = x·M, permuted along c'
__device__ __half g_ul[(size_t)B_ * T_ * C_];
__device__ __half g_wvh[(size_t)H_ * C_];
__device__ __half g_vth[(size_t)B_ * H_ * T_];   // v transposed: [b][h][t], hi only
__device__ __half g_weih[(size_t)B_ * T_ * T_];  // wei fp16 hi only

// ---------------- helpers ----------------
__device__ __forceinline__ uint32_t pack2(__half a, __half b) {
    __half2 h2 = __halves2half2(a, b);
    return *reinterpret_cast<uint32_t*>(&h2);
}
__device__ __forceinline__ void cpa16(uint32_t dst, const void* src) {
    asm volatile("cp.async.cg.shared.global [%0], [%1], 16;" :: "r"(dst), "l"(src));
}
__device__ __forceinline__ void cp_commit() {
    asm volatile("cp.async.commit_group;" ::: "memory");
}
template <int N>
__device__ __forceinline__ void cp_wait() {
    asm volatile("cp.async.wait_group %0;" :: "n"(N) : "memory");
}
__device__ __forceinline__ uint32_t smem_u32(const void* p) {
    uint32_t a;
    asm("{ .reg .u64 t; cvta.to.shared.u64 t, %1; cvt.u32.u64 %0, t; }" : "=r"(a) : "l"(p));
    return a;
}
// D += A*B, m16n8k16 fp16 inputs, fp32 accum
__device__ __forceinline__ void mma16(float* d, uint32_t a0, uint32_t a1, uint32_t a2,
                                      uint32_t a3, uint32_t b0, uint32_t b1) {
    asm volatile(
        "mma.sync.aligned.m16n8k16.row.col.f32.f16.f16.f32 "
        "{%0,%1,%2,%3},{%4,%5,%6,%7},{%8,%9},{%0,%1,%2,%3};"
        : "+f"(d[0]), "+f"(d[1]), "+f"(d[2]), "+f"(d[3])
        : "r"(a0), "r"(a1), "r"(a2), "r"(a3), "r"(b0), "r"(b1));
}
// permuted element index within 32-block (pair-level 4x4 transpose; involution)
__device__ __forceinline__ int pperm(int c) {
    const int p = (c & 31) >> 1;
    const int pp = ((p & 3) << 2) | (p >> 2);
    return (c & ~31) | (pp << 1) | (c & 1);
}

// ---------------- FP16 multi-pass NT GEMM via mma.sync (pair-permuted operands) ----------------
// C[m,n] = alpha * sum_k A[m,k]*B[n,k]. CTA 128x128, BK=32, 256 thr (2x4 warps).
// PASSES=3: AhBh + AlBh + AhBl.  PASSES=1: AhBh only.
// EPI=0: Cf = fp32*alpha (linear cols). EPI=1: Ch/Cl fp16 hi/lo (permuted cols).
// EPI=2: Ch fp16 hi only (permuted cols).
// causal: 0 none; 1 skip block if bn>bm; 2 Keff=min(K,(bm+1)*128), heavy-first bm remap.
static constexpr int GEMM_SMEM = 2 * 32768;   // 64 KB double buffer

template <int EPI, int PASSES>
__global__ __launch_bounds__(256, 2)
void mma_nt(const __half* __restrict__ Ahi, const __half* __restrict__ Alo,
            const __half* __restrict__ Bhi, const __half* __restrict__ Blo,
            float* __restrict__ Cf, __half* __restrict__ Ch, __half* __restrict__ Cl,
            int K, int lda, int ldb, int ldc,
            long long sA, long long sB, long long sC,
            float alpha, int causal)
{
    extern __shared__ char smc[];
    const int bn = blockIdx.x, bz = blockIdx.z;
    int bm = blockIdx.y;
    if (causal == 1 && bn > bm) return;
    if (causal == 2) bm = gridDim.y - 1 - bm;     // heavy tiles first
    int Keff = K;
    if (causal == 2) { int kl = (bm + 1) * 128; Keff = kl < K ? kl : K; }
    const int nk = Keff / 32;

    const __half* Ah = Ahi + (size_t)bz * sA;
    const __half* Al = (PASSES >= 2) ? Alo + (size_t)bz * sA : nullptr;
    const __half* Bh = Bhi + (size_t)bz * sB;
    const __half* Bl = (PASSES == 3) ? Blo + (size_t)bz * sB : nullptr;

    const int tid = threadIdx.x;
    const int lane = tid & 31, w = tid >> 5;
    const int wm = w & 1, wn = w >> 1;            // 2 (M) x 4 (N) warp grid
    const int gr = lane >> 2, tc = lane & 3;
    const uint32_t sbase = smem_u32(smc);

    // stage loader: arrays of [128][32] halves (64B rows); 512 16B-chunks each.
    auto load_stage = [&](int kt, int s) {
        const int k0 = kt * 32;
        const uint32_t dst = sbase + (uint32_t)s * 32768u;
#pragma unroll
        for (int t = 0; t < 2; t++) {
            const int idx = t * 256 + tid;         // 0..511
            const int row = idx >> 2, j = (idx & 3) * 8;
            const uint32_t off = (uint32_t)(row * 64 + j * 2);
            const size_t ga = (size_t)(bm * 128 + row) * lda + k0 + j;
            const size_t gb = (size_t)(bn * 128 + row) * ldb + k0 + j;
            cpa16(dst + off,           Ah + ga);
            if (PASSES >= 2) cpa16(dst + 8192u + off, Al + ga);
            cpa16(dst + 16384u + off,  Bh + gb);
            if (PASSES == 3) cpa16(dst + 24576u + off, Bl + gb);
        }
        cp_commit();
    };

    float acc[4][4][4];
#pragma unroll
    for (int i = 0; i < 4; i++)
#pragma unroll
        for (int j = 0; j < 4; j++)
#pragma unroll
            for (int r = 0; r < 4; r++) acc[i][j][r] = 0.f;

    load_stage(0, 0);

    const int rbA = (wm * 64 + gr) * 4 + tc;       // uint4 index of A frag row
    const int rbB = (wn * 32 + gr) * 4 + tc;

    for (int kt = 0; kt < nk; kt++) {
        const int s = kt & 1;
        cp_wait<0>();
        __syncthreads();                            // data(kt) visible; compute(kt-1) done
        if (kt + 1 < nk) load_stage(kt + 1, s ^ 1); // overlaps compute(kt)

        const uint4* S   = (const uint4*)(smc + s * 32768);
        const uint4* pAh = S;
        const uint4* pAl = S + 512;
        const uint4* pBh = S + 1024;
        const uint4* pBl = S + 1536;

        // B hi fragments: one uint4 per fn covers both k16 steps
        uint4 bh0 = pBh[rbB], bh1 = pBh[rbB + 32], bh2 = pBh[rbB + 64], bh3 = pBh[rbB + 96];

#pragma unroll
        for (int fm = 0; fm < 4; fm++) {
            const int ra = rbA + fm * 64;           // fm*16 rows * 4
            uint4 a0 = pAh[ra], a8 = pAh[ra + 32];  // rows gr, gr+8
            uint4 l0, l8;
            if (PASSES >= 2) { l0 = pAl[ra]; l8 = pAl[ra + 32]; }
#pragma unroll
            for (int fn = 0; fn < 4; fn++) {
                const uint4 bh = fn == 0 ? bh0 : fn == 1 ? bh1 : fn == 2 ? bh2 : bh3;
                float* a = acc[fm][fn];
                mma16(a, a0.x, a8.x, a0.y, a8.y, bh.x, bh.y);       // step0 hh
                if (PASSES >= 2) mma16(a, l0.x, l8.x, l0.y, l8.y, bh.x, bh.y);
                mma16(a, a0.z, a8.z, a0.w, a8.w, bh.z, bh.w);       // step1 hh
                if (PASSES >= 2) mma16(a, l0.z, l8.z, l0.w, l8.w, bh.z, bh.w);
            }
        }

        if (PASSES == 3) {                          // pass 3: hi*lo
            uint4 bl0 = pBl[rbB], bl1 = pBl[rbB + 32], bl2 = pBl[rbB + 64], bl3 = pBl[rbB + 96];
#pragma unroll
            for (int fm = 0; fm < 4; fm++) {
                const int ra = rbA + fm * 64;
                uint4 a0 = pAh[ra], a8 = pAh[ra + 32];
#pragma unroll
                for (int fn = 0; fn < 4; fn++) {
                    const uint4 bl = fn == 0 ? bl0 : fn == 1 ? bl1 : fn == 2 ? bl2 : bl3;
                    float* a = acc[fm][fn];
                    mma16(a, a0.x, a8.x, a0.y, a8.y, bl.x, bl.y);
                    mma16(a, a0.z, a8.z, a0.w, a8.w, bl.z, bl.w);
                }
            }
        }
    }

    // ---- epilogue ----
#pragma unroll
    for (int fm = 0; fm < 4; fm++) {
        const int r0 = bm * 128 + wm * 64 + fm * 16 + gr;
#pragma unroll
        for (int fn = 0; fn < 4; fn++) {
            const int c0 = bn * 128 + wn * 32 + fn * 8 + 2 * tc;
            const size_t b0 = (size_t)bz * sC + (size_t)r0 * ldc;
            const size_t b8 = b0 + (size_t)8 * ldc;
            const float* a = acc[fm][fn];
            if (EPI == 0) {
                *(float2*)(Cf + b0 + c0) = make_float2(a[0] * alpha, a[1] * alpha);
                *(float2*)(Cf + b8 + c0) = make_float2(a[2] * alpha, a[3] * alpha);
            } else {
                const int cp = pperm(c0);           // pair stays adjacent under pperm
                __half h0 = __float2half_rn(a[0]), h1 = __float2half_rn(a[1]);
                __half h2 = __float2half_rn(a[2]), h3 = __float2half_rn(a[3]);
                *(__half2*)(Ch + b0 + cp) = __halves2half2(h0, h1);
                *(__half2*)(Ch + b8 + cp) = __halves2half2(h2, h3);
                if (EPI == 1) {
                    *(__half2*)(Cl + b0 + cp) = __halves2half2(
                        __float2half_rn(a[0] - __half2float(h0)),
                        __float2half_rn(a[1] - __half2float(h1)));
                    *(__half2*)(Cl + b8 + cp) = __halves2half2(
                        __float2half_rn(a[2] - __half2float(h2)),
                        __float2half_rn(a[3] - __half2float(h3)));
                }
            }
        }
    }
}

// ---------------- elementwise fp16 split, writing pair-permuted layout ----------------
__global__ void split_kernel(const float* __restrict__ src,
                             __half* __restrict__ hi, __half* __restrict__ lo, int n8)
{
    const int i = blockIdx.x * blockDim.x + threadIdx.x;
    if (i >= n8) return;
    const int u = i & 3;
    const int blk = (i >> 2) * 32;
    uint32_t ho[4], lw[4];
#pragma unroll
    for (int b = 0; b < 4; b++) {
        const float2 v = *(const float2*)(src + blk + 8 * b + 2 * u);
        __half h0 = __float2half_rn(v.x), h1 = __float2half_rn(v.y);
        __half l0 = __float2half_rn(v.x - __half2float(h0));
        __half l1 = __float2half_rn(v.y - __half2float(h1));
        ho[b] = pack2(h0, h1);
        lw[b] = pack2(l0, l1);
    }
    ((uint2*)(hi + blk))[u * 2 + 0] = make_uint2(ho[0], ho[1]);
    ((uint2*)(hi + blk))[u * 2 + 1] = make_uint2(ho[2], ho[3]);
    if (lo) {
        ((uint2*)(lo + blk))[u * 2 + 0] = make_uint2(lw[0], lw[1]);
        ((uint2*)(lo + blk))[u * 2 + 1] = make_uint2(lw[2], lw[3]);
    }
}

// ---------------- transpose + fp16 split: W[H,C] fp32 -> Wt hi/lo [C,H], permuted along H ----------------
// Block handles a 64(h) x 32(c) tile; 256 threads.
__global__ __launch_bounds__(256)
void transpose_split_kernel(const float* __restrict__ W,
                            __half* __restrict__ th, __half* __restrict__ tl,
                            int Hd, int Cd)
{
    __shared__ float tile[64][33];
    const int c0 = blockIdx.x * 32, h0 = blockIdx.y * 64;
    const int tid = threadIdx.x;
    {
        const int lc = tid & 31;
        const int lh = tid >> 5;                    // 0..7
#pragma unroll
        for (int i = 0; i < 8; i++)
            tile[lh + 8 * i][lc] = W[(size_t)(h0 + lh + 8 * i) * Cd + c0 + lc];
    }
    __syncthreads();
    const int lc = tid >> 3;                        // 0..31 output row (c)
    const int lp = tid & 7;                         // pair-group
#pragma unroll
    for (int i = 0; i < 4; i++) {
        const int p = lp + 8 * i;                   // pair index 0..31 over 64 h
        const int b = p >> 4;                       // 32-elem block within the 64
        const int pin = p & 15;
        const int ppin = ((pin & 3) << 2) | (pin >> 2);
        const int hs = p * 2;
        const float v0 = tile[hs][lc], v1 = tile[hs + 1][lc];
        const __half h0_ = __float2half_rn(v0), h1_ = __float2half_rn(v1);
        const size_t o = (size_t)(c0 + lc) * Hd + h0 + b * 32 + ppin * 2;
        *(__half2*)(th + o) = __halves2half2(h0_, h1_);
        *(__half2*)(tl + o) = __halves2half2(__float2half_rn(v0 - __half2float(h0_)),
                                             __float2half_rn(v1 - __half2float(h1_)));
    }
}

// ---------------- single-sweep causal softmax + fp16 hi write (permuted cols) ----------------
__global__ __launch_bounds__(256)
void softmax_split_kernel(float* __restrict__ W, __half* __restrict__ Wh, int T)
{
    const long long row = blockIdx.x;
    const int t = (int)(row % T);
    float* p   = W  + row * (long long)T;
    __half* ph = Wh + row * (long long)T;
    const int n = t + 1;
    const int tid = threadIdx.x;
    const int base = tid * 8;

    __shared__ float red[8];

    float v[8];
    {
        float4 a = *(const float4*)(p + base);
        float4 b = *(const float4*)(p + base + 4);
        v[0] = a.x; v[1] = a.y; v[2] = a.z; v[3] = a.w;
        v[4] = b.x; v[5] = b.y; v[6] = b.z; v[7] = b.w;
    }
#pragma unroll
    for (int j = 0; j < 8; j++)
        if (base + j >= n) v[j] = -3.4e38f;

    float m = v[0];
#pragma unroll
    for (int j = 1; j < 8; j++) m = fmaxf(m, v[j]);
#pragma unroll
    for (int o = 16; o; o >>= 1) m = fmaxf(m, __shfl_xor_sync(0xffffffffu, m, o));
    if ((tid & 31) == 0) red[tid >> 5] = m;
    __syncthreads();
    if (tid < 32) {
        float mb = (tid < 8) ? red[tid] : -3.4e38f;
#pragma unroll
        for (int o = 4; o; o >>= 1) mb = fmaxf(mb, __shfl_xor_sync(0xffffffffu, mb, o));
        if (tid == 0) red[0] = mb;
    }
    __syncthreads();
    m = red[0];
    __syncthreads();

    float s = 0.f;
#pragma unroll
    for (int j = 0; j < 8; j++) {
        v[j] = (base + j < n) ? expf(v[j] - m) : 0.f;
        s += v[j];
    }
#pragma unroll
    for (int o = 16; o; o >>= 1) s += __shfl_xor_sync(0xffffffffu, s, o);
    if ((tid & 31) == 0) red[tid >> 5] = s;
    __syncthreads();
    if (tid < 32) {
        float sb = (tid < 8) ? red[tid] : 0.f;
#pragma unroll
        for (int o = 4; o; o >>= 1) sb += __shfl_xor_sync(0xffffffffu, sb, o);
        if (tid == 0) red[0] = sb;
    }
    __syncthreads();
    const float inv = 1.f / red[0];

#pragma unroll
    for (int j = 0; j < 8; j++) v[j] *= inv;
    *(float4*)(p + base)     = make_float4(v[0], v[1], v[2], v[3]);
    *(float4*)(p + base + 4) = make_float4(v[4], v[5], v[6], v[7]);

    const int u = tid & 3;
    __half* phb = ph + (base & ~31);
#pragma unroll
    for (int b = 0; b < 4; b++) {
        *(__half2*)(phb + (b * 4 + u) * 2) =
            __halves2half2(__float2half_rn(v[2 * b]), __float2half_rn(v[2 * b + 1]));
    }
}

// ---------------- launch ----------------
extern "C" void kernel_launch(void* const* d_in, const int* in_sizes, int n_in,
                              void* d_out, int out_size)
{
    (void)in_sizes; (void)n_in; (void)out_size;
    const float* x  = (const float*)d_in[0];
    const float* Wk = (const float*)d_in[1];
    const float* Wq = (const float*)d_in[2];
    const float* Wv = (const float*)d_in[3];

    float* out = (float*)d_out;                      // [B, T, H]
    float* wei = out + (size_t)B_ * T_ * H_;         // [B, T, T]

    __half *xh, *xl, *wqth, *wqtl, *wkth, *wktl, *mth, *mtl, *uh, *ul, *wvh, *vth, *weih;
    cudaGetSymbolAddress((void**)&xh, g_xh);     cudaGetSymbolAddress((void**)&xl, g_xl);
    cudaGetSymbolAddress((void**)&wqth, g_wqth); cudaGetSymbolAddress((void**)&wqtl, g_wqtl);
    cudaGetSymbolAddress((void**)&wkth, g_wkth); cudaGetSymbolAddress((void**)&wktl, g_wktl);
    cudaGetSymbolAddress((void**)&mth, g_mth);   cudaGetSymbolAddress((void**)&mtl, g_mtl);
    cudaGetSymbolAddress((void**)&uh, g_uh);     cudaGetSymbolAddress((void**)&ul, g_ul);
    cudaGetSymbolAddress((void**)&wvh, g_wvh);
    cudaGetSymbolAddress((void**)&vth, g_vth);
    cudaGetSymbolAddress((void**)&weih, g_weih);

    cudaFuncSetAttribute(mma_nt<0,3>, cudaFuncAttributeMaxDynamicSharedMemorySize, GEMM_SMEM);
    cudaFuncSetAttribute(mma_nt<1,3>, cudaFuncAttributeMaxDynamicSharedMemorySize, GEMM_SMEM);
    cudaFuncSetAttribute(mma_nt<2,1>, cudaFuncAttributeMaxDynamicSharedMemorySize, GEMM_SMEM);
    cudaFuncSetAttribute(mma_nt<0,1>, cudaFuncAttributeMaxDynamicSharedMemorySize, GEMM_SMEM);

    const dim3 blk(256);

    // 1) splits: x -> hi/lo; Wv -> hi only; Wq/Wk -> transposed hi/lo (permuted along H)
    {
        const int n8x = (B_ * T_ * C_) / 8;
        split_kernel<<<(n8x + 255) / 256, 256>>>(x, xh, xl, n8x);
        const int n8w = (H_ * C_) / 8;
        split_kernel<<<(n8w + 255) / 256, 256>>>(Wv, wvh, nullptr, n8w);
        const dim3 gt(C_ / 32, H_ / 64);
        transpose_split_kernel<<<gt, blk>>>(Wq, wqth, wqtl, H_, C_);
        transpose_split_kernel<<<gt, blk>>>(Wk, wkth, wktl, H_, C_);
    }

    // 2) Mt[c'][c] = sum_h Wk^T[c',h] * Wq^T[c,h]   (tiny: 1024x1024x1024, 3-pass)
    {
        const dim3 g(C_ / 128, C_ / 128, 1);
        mma_nt<1,3><<<g, blk, GEMM_SMEM>>>(wkth, wktl, wqth, wqtl, nullptr, mth, mtl,
                                           H_, H_, H_, C_, 0, 0, 0, 1.f, 0);
    }

    // 3) v: vT[b,h,t] = Wv_h[h,:]·x_h[b,t,:], 1-pass, hi-only output
    {
        const dim3 g(T_ / 128, H_ / 128, B_);
        mma_nt<2,1><<<g, blk, GEMM_SMEM>>>(wvh, nullptr, xh, nullptr, nullptr, vth, nullptr,
                                           C_, C_, C_, T_,
                                           0, (long long)T_ * C_, (long long)H_ * T_, 1.f, 0);
    }

    // 4) u[m,c'] = sum_c x[m,c] * Mt[c',c]   (M=B*T, N=C, K=C, 3-pass, hi/lo out)
    {
        const dim3 g(C_ / 128, (B_ * T_) / 128, 1);
        mma_nt<1,3><<<g, blk, GEMM_SMEM>>>(xh, xl, mth, mtl, nullptr, uh, ul,
                                           C_, C_, C_, C_, 0, 0, 0, 1.f, 0);
    }

    // 5) logits: wei[b,t,s] = (1/32) * sum_c' u[b,t,c'] * x[b,s,c']  (3-pass, causal skip)
    {
        const dim3 g(T_ / 128, T_ / 128, B_);
        mma_nt<0,3><<<g, blk, GEMM_SMEM>>>(uh, ul, xh, xl, wei, nullptr, nullptr,
                                           C_, C_, C_, T_,
                                           (long long)T_ * C_, (long long)T_ * C_,
                                           (long long)T_ * T_, 0.03125f, 1);
    }

    // 6) single-sweep causal softmax + permuted fp16 hi of wei
    softmax_split_kernel<<<B_ * T_, 256>>>(wei, weih, T_);

    // 7) out[b,t,h] = sum_s wei_h[b,t,s] * vT_h[b,h,s]  (1-pass, causal K, heavy-first)
    {
        const dim3 g(H_ / 128, T_ / 128, B_);
        mma_nt<0,1><<<g, blk, GEMM_SMEM>>>(weih, nullptr, vth, nullptr, out, nullptr, nullptr,
                                           T_, T_, T_, H_,
                                           (long long)T_ * T_, (long long)H_ * T_,
                                           (long long)T_ * H_, 1.f, 2);
    }
}